// round 1
// baseline (speedup 1.0000x reference)
#include <cuda_runtime.h>
#include <cuda_bf16.h>
#include <math.h>

// ---------------------------------------------------------------------------
// Problem constants
// ---------------------------------------------------------------------------
#define BB 4
#define NN 2048
#define DD 512
#define D1 1024          // 2*D
#define EE 512
#define NC 1024          // H*HD channels
#define ROWS (BB*NN)     // 8192
#define FFTN 4096
#define FFTH 2048
#define KSTRIDE 2049
#define LOGG (-1.0005003335835335e-3f)   // ln(0.999)

// ---------------------------------------------------------------------------
// Scratch (__device__ globals; no allocation allowed)
// ---------------------------------------------------------------------------
__device__ float  g_xn  [ROWS * DD];
__device__ float  g_u   [ROWS * D1];
__device__ float  g_v   [ROWS * D1];
__device__ float  g_vT  [BB * NC * NN];
__device__ float  g_conv[BB * NC * NN];
__device__ float  g_w   [ROWS * D1];
__device__ float  g_hcf [NN * EE];
__device__ float  g_act [NN * EE];
__device__ float  g_coef[NN * NC];
__device__ float  g_kT  [NC * NN];
__device__ float2 g_Ka  [NC * KSTRIDE];

// ---------------------------------------------------------------------------
// Helpers
// ---------------------------------------------------------------------------
__device__ __forceinline__ float2 cmul(float2 a, float2 b) {
    return make_float2(a.x*b.x - a.y*b.y, a.x*b.y + a.y*b.x);
}

// ---------------------------------------------------------------------------
// Row-wise srms (D=512), optional relu.  1 block (128 thr) per row.
// ---------------------------------------------------------------------------
__global__ void __launch_bounds__(128) rmsnorm_kernel(
    const float* __restrict__ in, float* __restrict__ out, int relu)
{
    size_t row = blockIdx.x;
    const float4* ip = (const float4*)(in + row * DD);
    float4 v = ip[threadIdx.x];
    float ss = v.x*v.x + v.y*v.y + v.z*v.z + v.w*v.w;
    #pragma unroll
    for (int o = 16; o; o >>= 1) ss += __shfl_xor_sync(0xffffffffu, ss, o);
    __shared__ float wsum[4];
    if ((threadIdx.x & 31) == 0) wsum[threadIdx.x >> 5] = ss;
    __syncthreads();
    float tot = wsum[0] + wsum[1] + wsum[2] + wsum[3];
    float inv = 1.0f / (sqrtf(tot * (1.0f / (float)DD)) + 1e-8f);
    float4 o4 = make_float4(v.x*inv, v.y*inv, v.z*inv, v.w*inv);
    if (relu) {
        o4.x = fmaxf(o4.x, 0.f); o4.y = fmaxf(o4.y, 0.f);
        o4.z = fmaxf(o4.z, 0.f); o4.w = fmaxf(o4.w, 0.f);
    }
    ((float4*)(out + row * DD))[threadIdx.x] = o4;
}

// ---------------------------------------------------------------------------
// hcf init: hcf[t,e] = t * Wp[e] + bp[e]
// ---------------------------------------------------------------------------
__global__ void hcf_init_kernel(const float* __restrict__ Wp,
                                const float* __restrict__ bp,
                                float* __restrict__ hcf)
{
    int i = blockIdx.x * blockDim.x + threadIdx.x;
    int t = i >> 9, e = i & 511;
    hcf[i] = (float)t * Wp[e] + bp[e];
}

// ---------------------------------------------------------------------------
// SGEMM: C[M,N] = A[M,K] @ B[K,N] + bias ; epi: 0=none, 1=silu, 2=+resid
// 128x128x8 tile, 256 threads, 8x8 per-thread. M,N mult of 128, K mult of 8.
// ---------------------------------------------------------------------------
__global__ void __launch_bounds__(256) sgemm_kernel(
    const float* __restrict__ A, const float* __restrict__ B,
    const float* __restrict__ bias, const float* __restrict__ resid,
    float* __restrict__ C, int M, int N, int K, int epi)
{
    __shared__ float As[8][128];
    __shared__ float Bs[8][128];
    const int tid = threadIdx.x;
    const int tx = tid & 15, ty = tid >> 4;
    const int rowBase = blockIdx.y * 128;
    const int colBase = blockIdx.x * 128;
    const int aRow = tid >> 1, aCol = (tid & 1) * 4;
    const int bRow = tid >> 5, bCol = (tid & 31) * 4;
    const float* Aptr = A + (size_t)(rowBase + aRow) * K + aCol;
    const float* Bptr = B + (size_t)bRow * N + colBase + bCol;
    float acc[8][8];
    #pragma unroll
    for (int i = 0; i < 8; i++)
        #pragma unroll
        for (int j = 0; j < 8; j++) acc[i][j] = 0.f;

    for (int k0 = 0; k0 < K; k0 += 8) {
        float4 av = *(const float4*)Aptr;  Aptr += 8;
        float4 bv = *(const float4*)Bptr;  Bptr += (size_t)8 * N;
        As[aCol+0][aRow] = av.x; As[aCol+1][aRow] = av.y;
        As[aCol+2][aRow] = av.z; As[aCol+3][aRow] = av.w;
        *(float4*)&Bs[bRow][bCol] = bv;
        __syncthreads();
        #pragma unroll
        for (int k = 0; k < 8; k++) {
            float4 a0 = *(const float4*)&As[k][ty*8];
            float4 a1 = *(const float4*)&As[k][ty*8+4];
            float4 b0 = *(const float4*)&Bs[k][tx*8];
            float4 b1 = *(const float4*)&Bs[k][tx*8+4];
            float ra[8] = {a0.x,a0.y,a0.z,a0.w,a1.x,a1.y,a1.z,a1.w};
            float rb[8] = {b0.x,b0.y,b0.z,b0.w,b1.x,b1.y,b1.z,b1.w};
            #pragma unroll
            for (int i = 0; i < 8; i++)
                #pragma unroll
                for (int j = 0; j < 8; j++)
                    acc[i][j] = fmaf(ra[i], rb[j], acc[i][j]);
        }
        __syncthreads();
    }

    #pragma unroll
    for (int i = 0; i < 8; i++) {
        int row = rowBase + ty*8 + i;
        #pragma unroll
        for (int j = 0; j < 8; j++) {
            int col = colBase + tx*8 + j;
            float c = acc[i][j] + bias[col];
            if (epi == 1) c = c / (1.0f + expf(-c));            // silu
            else if (epi == 2) c += resid[(size_t)row * N + col];
            C[(size_t)row * N + col] = c;
        }
    }
}

// ---------------------------------------------------------------------------
// Tiled transpose family (32x32 tiles, 32x8 threads)
// ---------------------------------------------------------------------------
// plain: in [z][R][C] -> out [z][C][R]
__global__ void transpose_kernel(const float* __restrict__ in,
                                 float* __restrict__ out, int R, int C)
{
    __shared__ float tile[32][33];
    const float* inb = in + (size_t)blockIdx.z * R * C;
    float* outb = out + (size_t)blockIdx.z * R * C;
    int x  = blockIdx.x * 32 + threadIdx.x;
    int y0 = blockIdx.y * 32;
    #pragma unroll
    for (int j = threadIdx.y; j < 32; j += 8)
        tile[j][threadIdx.x] = inb[(size_t)(y0 + j) * C + x];
    __syncthreads();
    int x2 = y0 + threadIdx.x;
    int y2 = blockIdx.x * 32;
    #pragma unroll
    for (int j = threadIdx.y; j < 32; j += 8)
        outb[(size_t)(y2 + j) * R + x2] = tile[threadIdx.x][j];
}

// coef [2048(t) x 1024(c)] -> kT [1024 x 2048] with decay gamma^t (t>0)
__global__ void decay_transpose_kernel(const float* __restrict__ in,
                                       float* __restrict__ out)
{
    __shared__ float tile[32][33];
    const int R = NN, C = NC;
    int x  = blockIdx.x * 32 + threadIdx.x;
    int y0 = blockIdx.y * 32;
    #pragma unroll
    for (int j = threadIdx.y; j < 32; j += 8) {
        int t = y0 + j;
        float fac = (t == 0) ? 1.0f : expf((float)t * LOGG);
        tile[j][threadIdx.x] = in[(size_t)t * C + x] * fac;
    }
    __syncthreads();
    int x2 = y0 + threadIdx.x;
    int y2 = blockIdx.x * 32;
    #pragma unroll
    for (int j = threadIdx.y; j < 32; j += 8)
        out[(size_t)(y2 + j) * R + x2] = tile[threadIdx.x][j];
}

// conv [b][1024(c)][2048(n)] -> w[b][2048(n)][1024(c)] multiplied by u[b][n][c]
__global__ void mul_transpose_kernel(const float* __restrict__ in,
                                     const float* __restrict__ u,
                                     float* __restrict__ out)
{
    __shared__ float tile[32][33];
    const int R = NC, C = NN;
    size_t boff = (size_t)blockIdx.z * R * C;
    const float* inb  = in  + boff;
    const float* ub   = u   + boff;
    float* outb       = out + boff;
    int x  = blockIdx.x * 32 + threadIdx.x;   // n
    int y0 = blockIdx.y * 32;                 // c
    #pragma unroll
    for (int j = threadIdx.y; j < 32; j += 8)
        tile[j][threadIdx.x] = inb[(size_t)(y0 + j) * C + x];
    __syncthreads();
    int x2 = y0 + threadIdx.x;                // c  (out col)
    int y2 = blockIdx.x * 32;                 // n base (out row)
    #pragma unroll
    for (int j = threadIdx.y; j < 32; j += 8) {
        int n = y2 + j;
        outb[(size_t)n * NC + x2] = tile[threadIdx.x][j] * ub[(size_t)n * NC + x2];
    }
}

// ---------------------------------------------------------------------------
// 4096-pt Stockham radix-2 FFT in shared memory (512 threads)
// Buffers: A[4096], B[4096], tw[2048]. Result ends in A (12 stages, even).
// ---------------------------------------------------------------------------
__device__ __forceinline__ void fft4096(float2* A, float2* Bb, const float2* tw,
                                        int tid, bool inv)
{
    float2* s = A; float2* d = Bb;
    int m = 1;
    for (int stage = 0; stage < 12; stage++) {
        __syncthreads();
        for (int p = tid; p < FFTH; p += 512) {
            int jm = p & ~(m - 1);
            float2 c0 = s[p], c1 = s[p + FFTH];
            float2 w = tw[jm];
            if (inv) w.y = -w.y;
            float2 dif = make_float2(c0.x - c1.x, c0.y - c1.y);
            d[p + jm]     = make_float2(c0.x + c1.x, c0.y + c1.y);
            d[p + jm + m] = make_float2(w.x*dif.x - w.y*dif.y,
                                        w.x*dif.y + w.y*dif.x);
        }
        float2* t = s; s = d; d = t;
        m <<= 1;
    }
    __syncthreads();
}

__device__ __forceinline__ void fill_tw(float2* tw, int tid)
{
    const float w0 = -1.5339807878856412e-3f;  // -2*pi/4096
    for (int k = tid; k < FFTH; k += 512) {
        float sv, cv;
        sincosf(w0 * (float)k, &sv, &cv);
        tw[k] = make_float2(cv, sv);
    }
}

// Forward FFT of kernel k[c,:] (two channels packed); stores Ka[c][0..2048]
// prescaled by 1/4096 (folds IFFT normalization).
__global__ void __launch_bounds__(512) ffta_kernel(
    const float* __restrict__ kT, float2* __restrict__ Ka)
{
    extern __shared__ float2 sm[];
    float2* A  = sm;
    float2* Bb = sm + FFTN;
    float2* tw = sm + 2*FFTN;
    int tid = threadIdx.x;
    int c0 = blockIdx.x * 2, c1 = c0 + 1;
    const float* ka = kT + (size_t)c0 * NN;
    const float* kb = ka + NN;
    for (int n2 = tid; n2 < NN; n2 += 512) A[n2] = make_float2(ka[n2], kb[n2]);
    for (int n2 = NN + tid; n2 < FFTN; n2 += 512) A[n2] = make_float2(0.f, 0.f);
    fill_tw(tw, tid);
    fft4096(A, Bb, tw, tid, false);
    const float S = 1.0f / (float)FFTN;
    for (int f = tid; f <= FFTH; f += 512) {
        int fm = (FFTN - f) & (FFTN - 1);
        float2 Zf = A[f], Zm = A[fm];
        float2 Va = make_float2(0.5f*(Zf.x + Zm.x), 0.5f*(Zf.y - Zm.y));
        float2 Vb = make_float2(0.5f*(Zf.y + Zm.y), 0.5f*(Zm.x - Zf.x));
        Ka[(size_t)c0 * KSTRIDE + f] = make_float2(Va.x * S, Va.y * S);
        Ka[(size_t)c1 * KSTRIDE + f] = make_float2(Vb.x * S, Vb.y * S);
    }
}

// Fused causal conv: FFT(v) -> pointwise * Ka -> IFFT -> conv out.
// One block per (b, channel-pair).
__global__ void __launch_bounds__(512) conv_kernel(
    const float* __restrict__ vT, const float2* __restrict__ Ka,
    float* __restrict__ convT)
{
    extern __shared__ float2 sm[];
    float2* A  = sm;
    float2* Bb = sm + FFTN;
    float2* tw = sm + 2*FFTN;
    int tid = threadIdx.x;
    int idx = blockIdx.x;
    int b = idx >> 9, cc = idx & 511;
    int c0 = cc * 2, c1 = c0 + 1;
    const float* va = vT + ((size_t)b * NC + c0) * NN;
    const float* vb = va + NN;
    for (int n2 = tid; n2 < NN; n2 += 512) A[n2] = make_float2(va[n2], vb[n2]);
    for (int n2 = NN + tid; n2 < FFTN; n2 += 512) A[n2] = make_float2(0.f, 0.f);
    fill_tw(tw, tid);
    fft4096(A, Bb, tw, tid, false);

    const float2* K0 = Ka + (size_t)c0 * KSTRIDE;
    const float2* K1 = Ka + (size_t)c1 * KSTRIDE;
    for (int f = tid; f <= FFTH; f += 512) {
        int fm = (FFTN - f) & (FFTN - 1);
        float2 Zf = A[f], Zm = A[fm];
        float2 Va = make_float2(0.5f*(Zf.x + Zm.x), 0.5f*(Zf.y - Zm.y));
        float2 Vb = make_float2(0.5f*(Zf.y + Zm.y), 0.5f*(Zm.x - Zf.x));
        float2 Ya = cmul(Va, K0[f]);
        float2 Yb = cmul(Vb, K1[f]);
        A[f] = make_float2(Ya.x - Yb.y, Ya.y + Yb.x);          // Ya + i Yb
        if (f != 0 && f != FFTH)
            A[fm] = make_float2(Ya.x + Yb.y, Yb.x - Ya.y);     // conj(Ya)+i conj(Yb)
    }
    fft4096(A, Bb, tw, tid, true);

    float* oa = convT + ((size_t)b * NC + c0) * NN;
    for (int n2 = tid; n2 < NN; n2 += 512) {
        oa[n2]      = A[n2].x;
        oa[NN + n2] = A[n2].y;
    }
}

// ---------------------------------------------------------------------------
// Launch
// ---------------------------------------------------------------------------
extern "C" void kernel_launch(void* const* d_in, const int* in_sizes, int n_in,
                              void* d_out, int out_size)
{
    const float* x  = (const float*)d_in[0];
    const float* Wu = (const float*)d_in[1];
    const float* bu = (const float*)d_in[2];
    const float* Wv = (const float*)d_in[3];
    const float* bv = (const float*)d_in[4];
    const float* Wo = (const float*)d_in[5];
    const float* bo = (const float*)d_in[6];
    const float* Wp = (const float*)d_in[7];
    const float* bp = (const float*)d_in[8];
    const float* W1 = (const float*)d_in[9];
    const float* b1 = (const float*)d_in[10];
    const float* W2 = (const float*)d_in[11];
    const float* b2 = (const float*)d_in[12];
    const float* W3 = (const float*)d_in[13];
    const float* b3 = (const float*)d_in[14];
    const float* Wz = (const float*)d_in[15];
    const float* bz = (const float*)d_in[16];
    float* y = (float*)d_out;

    float  *p_xn, *p_u, *p_v, *p_vT, *p_conv, *p_w, *p_hcf, *p_act, *p_coef, *p_kT;
    float2 *p_Ka;
    cudaGetSymbolAddress((void**)&p_xn,   g_xn);
    cudaGetSymbolAddress((void**)&p_u,    g_u);
    cudaGetSymbolAddress((void**)&p_v,    g_v);
    cudaGetSymbolAddress((void**)&p_vT,   g_vT);
    cudaGetSymbolAddress((void**)&p_conv, g_conv);
    cudaGetSymbolAddress((void**)&p_w,    g_w);
    cudaGetSymbolAddress((void**)&p_hcf,  g_hcf);
    cudaGetSymbolAddress((void**)&p_act,  g_act);
    cudaGetSymbolAddress((void**)&p_coef, g_coef);
    cudaGetSymbolAddress((void**)&p_kT,   g_kT);
    cudaGetSymbolAddress((void**)&p_Ka,   g_Ka);

    const int FFT_SMEM = (2 * FFTN + FFTH) * sizeof(float2);   // 81920 B
    cudaFuncSetAttribute(ffta_kernel, cudaFuncAttributeMaxDynamicSharedMemorySize, FFT_SMEM);
    cudaFuncSetAttribute(conv_kernel, cudaFuncAttributeMaxDynamicSharedMemorySize, FFT_SMEM);

    // 1. xn = srms(x)
    rmsnorm_kernel<<<ROWS, 128>>>(x, p_xn, 0);

    // 2. u = silu(xn@Wu + bu), v = silu(xn@Wv + bv)
    sgemm_kernel<<<dim3(D1/128, ROWS/128), 256>>>(p_xn, Wu, bu, nullptr, p_u,
                                                  ROWS, D1, DD, 1);
    sgemm_kernel<<<dim3(D1/128, ROWS/128), 256>>>(p_xn, Wv, bv, nullptr, p_v,
                                                  ROWS, D1, DD, 1);

    // 3. vT[b][c][n] <- v[b][n][c]
    transpose_kernel<<<dim3(NC/32, NN/32, BB), dim3(32, 8)>>>(p_v, p_vT, NN, NC);

    // 4. position MLP -> coef
    hcf_init_kernel<<<(NN*EE)/256, 256>>>(Wp, bp, p_hcf);
    const float* Ws[3] = {W1, W2, W3};
    const float* bs[3] = {b1, b2, b3};
    for (int l = 0; l < 3; l++) {
        rmsnorm_kernel<<<NN, 128>>>(p_hcf, p_act, 1);
        sgemm_kernel<<<dim3(EE/128, NN/128), 256>>>(p_act, Ws[l], bs[l], nullptr,
                                                    p_hcf, NN, EE, EE, 0);
    }
    rmsnorm_kernel<<<NN, 128>>>(p_hcf, p_act, 1);
    sgemm_kernel<<<dim3(NC/128, NN/128), 256>>>(p_act, Wz, bz, nullptr,
                                                p_coef, NN, NC, EE, 0);

    // 5. kT[c][t] = decay(t) * coef[t][c]
    decay_transpose_kernel<<<dim3(NC/32, NN/32), dim3(32, 8)>>>(p_coef, p_kT);

    // 6. Ka[c][f] = rfft(kT[c], 4096) / 4096
    ffta_kernel<<<NC/2, 512, FFT_SMEM>>>(p_kT, p_Ka);

    // 7. causal conv per channel (FFT -> x Ka -> IFFT)
    conv_kernel<<<BB * NC / 2, 512, FFT_SMEM>>>(p_vT, p_Ka, p_conv);

    // 8. w[b][n][c] = u[b][n][c] * conv[b][c][n]
    mul_transpose_kernel<<<dim3(NN/32, NC/32, BB), dim3(32, 8)>>>(p_conv, p_u, p_w);

    // 9. y = w @ Wo + bo + x
    sgemm_kernel<<<dim3(DD/128, ROWS/128), 256>>>(p_w, Wo, bo, x, y,
                                                  ROWS, DD, D1, 2);
}

// round 5
// speedup vs baseline: 2.2078x; 2.2078x over previous
#include <cuda_runtime.h>
#include <cuda_bf16.h>
#include <math.h>
#include <stdint.h>

// ---------------------------------------------------------------------------
// Problem constants
// ---------------------------------------------------------------------------
#define BB 4
#define NN 2048
#define DD 512
#define D1 1024          // 2*D
#define EE 512
#define NC 1024          // H*HD channels
#define ROWS (BB*NN)     // 8192
#define FFTN 4096
#define FFTH 2048
#define KSTRIDE 2049
#define LOGG (-1.0005003335835335e-3f)   // ln(0.999)

// ---------------------------------------------------------------------------
// Scratch (__device__ globals; no allocation allowed)
// ---------------------------------------------------------------------------
__device__ __nv_bfloat16 g_xn_hi[ROWS * DD], g_xn_lo[ROWS * DD];
__device__ __nv_bfloat16 g_act_hi[NN * EE],  g_act_lo[NN * EE];
__device__ __nv_bfloat16 g_w_hi [ROWS * D1], g_w_lo [ROWS * D1];

__device__ __nv_bfloat16 g_WuT_hi[D1 * DD], g_WuT_lo[D1 * DD];
__device__ __nv_bfloat16 g_WvT_hi[D1 * DD], g_WvT_lo[D1 * DD];
__device__ __nv_bfloat16 g_WoT_hi[DD * D1], g_WoT_lo[DD * D1];
__device__ __nv_bfloat16 g_W1T_hi[EE * EE], g_W1T_lo[EE * EE];
__device__ __nv_bfloat16 g_W2T_hi[EE * EE], g_W2T_lo[EE * EE];
__device__ __nv_bfloat16 g_W3T_hi[EE * EE], g_W3T_lo[EE * EE];
__device__ __nv_bfloat16 g_WzT_hi[NC * EE], g_WzT_lo[NC * EE];

__device__ float  g_u   [ROWS * D1];
__device__ float  g_vT  [BB * NC * NN];
__device__ float  g_conv[BB * NC * NN];
__device__ float  g_hcf [NN * EE];
__device__ float  g_kT  [NC * NN];
__device__ float2 g_Ka  [NC * KSTRIDE];

// ---------------------------------------------------------------------------
// Helpers
// ---------------------------------------------------------------------------
__device__ __forceinline__ uint32_t smem_u32(const void* p) {
    uint32_t a;
    asm("{ .reg .u64 t; cvta.to.shared.u64 t, %1; cvt.u32.u64 %0, t; }"
        : "=r"(a) : "l"(p));
    return a;
}

__device__ __forceinline__ uint32_t packbf(float a, float b) {
    __nv_bfloat162 t;
    t.x = __float2bfloat16(a);
    t.y = __float2bfloat16(b);
    return *reinterpret_cast<uint32_t*>(&t);
}

__device__ __forceinline__ float2 cmul(float2 a, float2 b) {
    return make_float2(a.x*b.x - a.y*b.y, a.x*b.y + a.y*b.x);
}

__device__ __forceinline__ void ldmx4(uint32_t* r, uint32_t addr) {
    asm volatile("ldmatrix.sync.aligned.m8n8.x4.shared.b16 {%0,%1,%2,%3}, [%4];"
                 : "=r"(r[0]), "=r"(r[1]), "=r"(r[2]), "=r"(r[3]) : "r"(addr));
}
__device__ __forceinline__ void ldmx2(uint32_t* r, uint32_t addr) {
    asm volatile("ldmatrix.sync.aligned.m8n8.x2.shared.b16 {%0,%1}, [%2];"
                 : "=r"(r[0]), "=r"(r[1]) : "r"(addr));
}
__device__ __forceinline__ void mma16816(float* d, const uint32_t* a, const uint32_t* b) {
    asm volatile(
        "mma.sync.aligned.m16n8k16.row.col.f32.bf16.bf16.f32 "
        "{%0,%1,%2,%3}, {%4,%5,%6,%7}, {%8,%9}, {%0,%1,%2,%3};"
        : "+f"(d[0]), "+f"(d[1]), "+f"(d[2]), "+f"(d[3])
        : "r"(a[0]), "r"(a[1]), "r"(a[2]), "r"(a[3]), "r"(b[0]), "r"(b[1]));
}

// ---------------------------------------------------------------------------
// Row-wise srms (width 512) -> hi/lo bf16 split, optional relu.
// ---------------------------------------------------------------------------
__global__ void __launch_bounds__(128) rmsnorm_bf16_kernel(
    const float* __restrict__ in,
    __nv_bfloat16* __restrict__ hi, __nv_bfloat16* __restrict__ lo, int relu)
{
    size_t row = blockIdx.x;
    const float4* ip = (const float4*)(in + row * DD);
    float4 v = ip[threadIdx.x];
    float ss = v.x*v.x + v.y*v.y + v.z*v.z + v.w*v.w;
    #pragma unroll
    for (int o = 16; o; o >>= 1) ss += __shfl_xor_sync(0xffffffffu, ss, o);
    __shared__ float wsum[4];
    if ((threadIdx.x & 31) == 0) wsum[threadIdx.x >> 5] = ss;
    __syncthreads();
    float tot = wsum[0] + wsum[1] + wsum[2] + wsum[3];
    float inv = 1.0f / (sqrtf(tot * (1.0f / (float)DD)) + 1e-8f);
    float o4[4] = {v.x*inv, v.y*inv, v.z*inv, v.w*inv};
    if (relu) {
        #pragma unroll
        for (int i = 0; i < 4; i++) o4[i] = fmaxf(o4[i], 0.f);
    }
    float l4[4];
    #pragma unroll
    for (int i = 0; i < 4; i++)
        l4[i] = o4[i] - __bfloat162float(__float2bfloat16(o4[i]));
    size_t base = row * DD + threadIdx.x * 4;
    *(uint2*)(hi + base) = make_uint2(packbf(o4[0], o4[1]), packbf(o4[2], o4[3]));
    *(uint2*)(lo + base) = make_uint2(packbf(l4[0], l4[1]), packbf(l4[2], l4[3]));
}

// ---------------------------------------------------------------------------
// Weight transpose+convert: W[K][N] fp32 -> T_hi/T_lo [N][K] bf16
// ---------------------------------------------------------------------------
__global__ void convT_kernel(const float* __restrict__ W,
                             __nv_bfloat16* __restrict__ Thi,
                             __nv_bfloat16* __restrict__ Tlo, int K, int N)
{
    __shared__ float tile[32][33];
    int n0 = blockIdx.x * 32, k0 = blockIdx.y * 32;
    #pragma unroll
    for (int j = threadIdx.y; j < 32; j += 8)
        tile[j][threadIdx.x] = W[(size_t)(k0 + j) * N + n0 + threadIdx.x];
    __syncthreads();
    #pragma unroll
    for (int j = threadIdx.y; j < 32; j += 8) {
        float v = tile[threadIdx.x][j];
        __nv_bfloat16 h = __float2bfloat16(v);
        float r = v - __bfloat162float(h);
        size_t idx = (size_t)(n0 + j) * K + k0 + threadIdx.x;
        Thi[idx] = h;
        Tlo[idx] = __float2bfloat16(r);
    }
}

// ---------------------------------------------------------------------------
// hcf init: hcf[t,e] = t * Wp[e] + bp[e]
// ---------------------------------------------------------------------------
__global__ void hcf_init_kernel(const float* __restrict__ Wp,
                                const float* __restrict__ bp,
                                float* __restrict__ hcf)
{
    int i = blockIdx.x * blockDim.x + threadIdx.x;
    int t = i >> 9, e = i & 511;
    hcf[i] = (float)t * Wp[e] + bp[e];
}

// ---------------------------------------------------------------------------
// HMMA bf16-split GEMM: C[M,N] = (Ahi+Alo)[M,K] @ (Bhi+Blo)[N,K]^T + bias
// epi: 0 plain rowmajor / 1 silu rowmajor / 2 silu -> vT[b][c][n]
//      3 +resid rowmajor / 4 decay -> kT[c][t]
// Tile 128x128, Kc=64, cp.async loads, SW128 xor swizzle, mma.sync m16n8k16.
// 256 threads: 8 warps in 4(M) x 2(N), warp tile 32x64.
// ---------------------------------------------------------------------------
#define KC 64
#define TILE_B 16384                      // 128 rows x 128 bytes
#define GEMM_SMEM (128*132*4)             // fp32 C staging (67584 B) >= 4*TILE_B

__global__ void __launch_bounds__(256, 2)
hgemm_kernel(const __nv_bfloat16* __restrict__ Ahi, const __nv_bfloat16* __restrict__ Alo,
             const __nv_bfloat16* __restrict__ Bhi, const __nv_bfloat16* __restrict__ Blo,
             const float* __restrict__ bias, const float* __restrict__ resid,
             float* __restrict__ out, int M, int N, int K, int epi)
{
    extern __shared__ char smraw[];
    float* smC = (float*)smraw;
    const uint32_t sbase = smem_u32(smraw);

    const int tid = threadIdx.x, wid = tid >> 5, lane = tid & 31;
    const int m0 = blockIdx.y * 128, n0 = blockIdx.x * 128;
    const int wm = (wid & 3) * 32, wn = (wid >> 2) * 64;

    float acc[2][8][4];
    #pragma unroll
    for (int i = 0; i < 2; i++)
        #pragma unroll
        for (int j = 0; j < 8; j++)
            #pragma unroll
            for (int q = 0; q < 4; q++) acc[i][j][q] = 0.f;

    const int lr = tid >> 3;     // 0..31 (row group)
    const int lc = tid & 7;      // 16B chunk in row

    const int nch = K / KC;
    for (int ch = 0; ch < nch; ch++) {
        const int k0 = ch * KC;
        // ---- load 4 operand tiles via cp.async (each 128 rows x 128B) ----
        #pragma unroll
        for (int t4 = 0; t4 < 4; t4++) {
            const __nv_bfloat16* src =
                ((t4 == 0) ? Ahi : (t4 == 1) ? Alo : (t4 == 2) ? Bhi : Blo)
                + (size_t)((t4 < 2) ? m0 : n0) * K + k0 + lc * 8;
            uint32_t sdst = sbase + t4 * TILE_B;
            #pragma unroll
            for (int rr = 0; rr < 4; rr++) {
                int r = lr + rr * 32;
                uint32_t off = (uint32_t)(r * 128 + lc * 16);
                off ^= (off >> 3) & 0x70u;
                asm volatile("cp.async.cg.shared.global [%0], [%1], 16;"
                             :: "r"(sdst + off), "l"(src + (size_t)r * K) : "memory");
            }
        }
        asm volatile("cp.async.commit_group;" ::: "memory");
        asm volatile("cp.async.wait_group 0;" ::: "memory");
        __syncthreads();

        // ---- pass 1: AH x BH and AL x BH ----
        #pragma unroll
        for (int ks = 0; ks < 4; ks++) {
            uint32_t ah[2][4], al[2][4], bh[8][2];
            #pragma unroll
            for (int mt = 0; mt < 2; mt++) {
                uint32_t off = (uint32_t)((wm + mt*16 + (lane & 15)) * 128
                                          + ks * 32 + ((lane >> 4) & 1) * 16);
                off ^= (off >> 3) & 0x70u;
                ldmx4(ah[mt], sbase + off);
                ldmx4(al[mt], sbase + TILE_B + off);
            }
            #pragma unroll
            for (int nt = 0; nt < 8; nt++) {
                uint32_t off = (uint32_t)((wn + nt*8 + (lane & 7)) * 128
                                          + ks * 32 + ((lane >> 3) & 1) * 16);
                off ^= (off >> 3) & 0x70u;
                ldmx2(bh[nt], sbase + 2 * TILE_B + off);
            }
            #pragma unroll
            for (int mt = 0; mt < 2; mt++)
                #pragma unroll
                for (int nt = 0; nt < 8; nt++) {
                    mma16816(acc[mt][nt], ah[mt], bh[nt]);
                    mma16816(acc[mt][nt], al[mt], bh[nt]);
                }
        }
        // ---- pass 2: AH x BL ----
        #pragma unroll
        for (int ks = 0; ks < 4; ks++) {
            uint32_t ah[2][4], bl[8][2];
            #pragma unroll
            for (int mt = 0; mt < 2; mt++) {
                uint32_t off = (uint32_t)((wm + mt*16 + (lane & 15)) * 128
                                          + ks * 32 + ((lane >> 4) & 1) * 16);
                off ^= (off >> 3) & 0x70u;
                ldmx4(ah[mt], sbase + off);
            }
            #pragma unroll
            for (int nt = 0; nt < 8; nt++) {
                uint32_t off = (uint32_t)((wn + nt*8 + (lane & 7)) * 128
                                          + ks * 32 + ((lane >> 3) & 1) * 16);
                off ^= (off >> 3) & 0x70u;
                ldmx2(bl[nt], sbase + 3 * TILE_B + off);
            }
            #pragma unroll
            for (int mt = 0; mt < 2; mt++)
                #pragma unroll
                for (int nt = 0; nt < 8; nt++)
                    mma16816(acc[mt][nt], ah[mt], bl[nt]);
        }
        __syncthreads();
    }

    // ---- stage C in smem [128][132] fp32 ----
    #pragma unroll
    for (int mt = 0; mt < 2; mt++)
        #pragma unroll
        for (int nt = 0; nt < 8; nt++) {
            int r0 = wm + mt*16 + (lane >> 2);
            int c0 = wn + nt*8 + (lane & 3)*2;
            smC[r0*132 + c0]        = acc[mt][nt][0];
            smC[r0*132 + c0 + 1]    = acc[mt][nt][1];
            smC[(r0+8)*132 + c0]    = acc[mt][nt][2];
            smC[(r0+8)*132 + c0 + 1]= acc[mt][nt][3];
        }
    __syncthreads();

    if (epi == 0 || epi == 1 || epi == 3) {
        #pragma unroll 1
        for (int g = 0; g < 8; g++) {
            int row = g*16 + (tid >> 4);
            int col = (tid & 15) * 8;
            float vv[8];
            *(float4*)&vv[0] = *(float4*)&smC[row*132 + col];
            *(float4*)&vv[4] = *(float4*)&smC[row*132 + col + 4];
            const float* rp = (epi == 3) ? resid + (size_t)(m0+row)*N + n0 + col : nullptr;
            #pragma unroll
            for (int j = 0; j < 8; j++) {
                float c = vv[j] + bias[n0 + col + j];
                if (epi == 1) c = c / (1.0f + __expf(-c));
                else if (epi == 3) c += rp[j];
                vv[j] = c;
            }
            float* op = out + (size_t)(m0+row)*N + n0 + col;
            *(float4*)&op[0] = *(float4*)&vv[0];
            *(float4*)&op[4] = *(float4*)&vv[4];
        }
    } else {
        // epi 2: silu -> vT[b][c][n];  epi 4: decay -> kT[c][t]
        const int bb = m0 >> 11;
        const int nb = m0 & (NN - 1);
        #pragma unroll 1
        for (int g = 0; g < 16; g++) {
            int c  = (tid >> 5) * 16 + g;
            int nq = lane * 4;
            float b = bias[n0 + c];
            const float* cp = &smC[nq*132 + c];
            float vv[4] = { cp[0], cp[132], cp[264], cp[396] };
            if (epi == 2) {
                #pragma unroll
                for (int j = 0; j < 4; j++) {
                    float t = vv[j] + b;
                    vv[j] = t / (1.0f + __expf(-t));
                }
                float* op = out + (size_t)bb*NC*NN + (size_t)(n0+c)*NN + nb + nq;
                *(float4*)op = *(float4*)vv;
            } else {
                #pragma unroll
                for (int j = 0; j < 4; j++) {
                    int t = m0 + nq + j;
                    float fac = (t == 0) ? 1.0f : __expf((float)t * LOGG);
                    vv[j] = (vv[j] + b) * fac;
                }
                float* op = out + (size_t)(n0+c)*NN + m0 + nq;
                *(float4*)op = *(float4*)vv;
            }
        }
    }
}

// ---------------------------------------------------------------------------
// conv [b][c][n] * u [b][n][c] -> w_hi/w_lo bf16 [b][n][c]
// ---------------------------------------------------------------------------
__global__ void mul_transpose_kernel(const float* __restrict__ in,
                                     const float* __restrict__ u,
                                     __nv_bfloat16* __restrict__ whi,
                                     __nv_bfloat16* __restrict__ wlo)
{
    __shared__ float tile[32][33];
    size_t boff = (size_t)blockIdx.z * NC * NN;
    const float* inb = in + boff;
    const float* ub  = u  + boff;
    int x  = blockIdx.x * 32 + threadIdx.x;   // n
    int y0 = blockIdx.y * 32;                 // c
    #pragma unroll
    for (int j = threadIdx.y; j < 32; j += 8)
        tile[j][threadIdx.x] = inb[(size_t)(y0 + j) * NN + x];
    __syncthreads();
    int x2 = y0 + threadIdx.x;                // c
    int y2 = blockIdx.x * 32;                 // n base
    #pragma unroll
    for (int j = threadIdx.y; j < 32; j += 8) {
        int n = y2 + j;
        size_t idx = boff + (size_t)n * NC + x2;
        float f = tile[threadIdx.x][j] * ub[(size_t)n * NC + x2];
        __nv_bfloat16 h = __float2bfloat16(f);
        whi[idx] = h;
        wlo[idx] = __float2bfloat16(f - __bfloat162float(h));
    }
}

// ---------------------------------------------------------------------------
// 4096-pt Stockham radix-2 FFT in shared memory (512 threads)
// ---------------------------------------------------------------------------
__device__ __forceinline__ void fft4096(float2* A, float2* Bb, const float2* tw,
                                        int tid, bool inv)
{
    float2* s = A; float2* d = Bb;
    int m = 1;
    for (int stage = 0; stage < 12; stage++) {
        __syncthreads();
        for (int p = tid; p < FFTH; p += 512) {
            int jm = p & ~(m - 1);
            float2 c0 = s[p], c1 = s[p + FFTH];
            float2 w = tw[jm];
            if (inv) w.y = -w.y;
            float2 dif = make_float2(c0.x - c1.x, c0.y - c1.y);
            d[p + jm]     = make_float2(c0.x + c1.x, c0.y + c1.y);
            d[p + jm + m] = make_float2(w.x*dif.x - w.y*dif.y,
                                        w.x*dif.y + w.y*dif.x);
        }
        float2* t = s; s = d; d = t;
        m <<= 1;
    }
    __syncthreads();
}

__device__ __forceinline__ void fill_tw(float2* tw, int tid)
{
    const float w0 = -1.5339807878856412e-3f;  // -2*pi/4096
    for (int k = tid; k < FFTH; k += 512) {
        float sv, cv;
        sincosf(w0 * (float)k, &sv, &cv);
        tw[k] = make_float2(cv, sv);
    }
}

__global__ void __launch_bounds__(512) ffta_kernel(
    const float* __restrict__ kT, float2* __restrict__ Ka)
{
    extern __shared__ float2 sm[];
    float2* A  = sm;
    float2* Bb = sm + FFTN;
    float2* tw = sm + 2*FFTN;
    int tid = threadIdx.x;
    int c0 = blockIdx.x * 2, c1 = c0 + 1;
    const float* ka = kT + (size_t)c0 * NN;
    const float* kb = ka + NN;
    for (int n2 = tid; n2 < NN; n2 += 512) A[n2] = make_float2(ka[n2], kb[n2]);
    for (int n2 = NN + tid; n2 < FFTN; n2 += 512) A[n2] = make_float2(0.f, 0.f);
    fill_tw(tw, tid);
    fft4096(A, Bb, tw, tid, false);
    const float S = 1.0f / (float)FFTN;
    for (int f = tid; f <= FFTH; f += 512) {
        int fm = (FFTN - f) & (FFTN - 1);
        float2 Zf = A[f], Zm = A[fm];
        float2 Va = make_float2(0.5f*(Zf.x + Zm.x), 0.5f*(Zf.y - Zm.y));
        float2 Vb = make_float2(0.5f*(Zf.y + Zm.y), 0.5f*(Zm.x - Zf.x));
        Ka[(size_t)c0 * KSTRIDE + f] = make_float2(Va.x * S, Va.y * S);
        Ka[(size_t)c1 * KSTRIDE + f] = make_float2(Vb.x * S, Vb.y * S);
    }
}

__global__ void __launch_bounds__(512) conv_kernel(
    const float* __restrict__ vT, const float2* __restrict__ Ka,
    float* __restrict__ convT)
{
    extern __shared__ float2 sm[];
    float2* A  = sm;
    float2* Bb = sm + FFTN;
    float2* tw = sm + 2*FFTN;
    int tid = threadIdx.x;
    int idx = blockIdx.x;
    int b = idx >> 9, cc = idx & 511;
    int c0 = cc * 2, c1 = c0 + 1;
    const float* va = vT + ((size_t)b * NC + c0) * NN;
    const float* vb = va + NN;
    for (int n2 = tid; n2 < NN; n2 += 512) A[n2] = make_float2(va[n2], vb[n2]);
    for (int n2 = NN + tid; n2 < FFTN; n2 += 512) A[n2] = make_float2(0.f, 0.f);
    fill_tw(tw, tid);
    fft4096(A, Bb, tw, tid, false);

    const float2* K0 = Ka + (size_t)c0 * KSTRIDE;
    const float2* K1 = Ka + (size_t)c1 * KSTRIDE;
    for (int f = tid; f <= FFTH; f += 512) {
        int fm = (FFTN - f) & (FFTN - 1);
        float2 Zf = A[f], Zm = A[fm];
        float2 Va = make_float2(0.5f*(Zf.x + Zm.x), 0.5f*(Zf.y - Zm.y));
        float2 Vb = make_float2(0.5f*(Zf.y + Zm.y), 0.5f*(Zm.x - Zf.x));
        float2 Ya = cmul(Va, K0[f]);
        float2 Yb = cmul(Vb, K1[f]);
        A[f] = make_float2(Ya.x - Yb.y, Ya.y + Yb.x);
        if (f != 0 && f != FFTH)
            A[fm] = make_float2(Ya.x + Yb.y, Yb.x - Ya.y);
    }
    fft4096(A, Bb, tw, tid, true);

    float* oa = convT + ((size_t)b * NC + c0) * NN;
    for (int n2 = tid; n2 < NN; n2 += 512) {
        oa[n2]      = A[n2].x;
        oa[NN + n2] = A[n2].y;
    }
}

// ---------------------------------------------------------------------------
// Launch
// ---------------------------------------------------------------------------
extern "C" void kernel_launch(void* const* d_in, const int* in_sizes, int n_in,
                              void* d_out, int out_size)
{
    const float* x  = (const float*)d_in[0];
    const float* Wu = (const float*)d_in[1];
    const float* bu = (const float*)d_in[2];
    const float* Wv = (const float*)d_in[3];
    const float* bv = (const float*)d_in[4];
    const float* Wo = (const float*)d_in[5];
    const float* bo = (const float*)d_in[6];
    const float* Wp = (const float*)d_in[7];
    const float* bp = (const float*)d_in[8];
    const float* W1 = (const float*)d_in[9];
    const float* b1 = (const float*)d_in[10];
    const float* W2 = (const float*)d_in[11];
    const float* b2 = (const float*)d_in[12];
    const float* W3 = (const float*)d_in[13];
    const float* b3 = (const float*)d_in[14];
    const float* Wz = (const float*)d_in[15];
    const float* bz = (const float*)d_in[16];
    float* y = (float*)d_out;

    __nv_bfloat16 *p_xn_hi, *p_xn_lo, *p_act_hi, *p_act_lo, *p_w_hi, *p_w_lo;
    __nv_bfloat16 *p_WuT_hi, *p_WuT_lo, *p_WvT_hi, *p_WvT_lo, *p_WoT_hi, *p_WoT_lo;
    __nv_bfloat16 *p_W1T_hi, *p_W1T_lo, *p_W2T_hi, *p_W2T_lo, *p_W3T_hi, *p_W3T_lo;
    __nv_bfloat16 *p_WzT_hi, *p_WzT_lo;
    float *p_u, *p_vT, *p_conv, *p_hcf, *p_kT;
    float2 *p_Ka;

    cudaGetSymbolAddress((void**)&p_xn_hi, g_xn_hi);
    cudaGetSymbolAddress((void**)&p_xn_lo, g_xn_lo);
    cudaGetSymbolAddress((void**)&p_act_hi, g_act_hi);
    cudaGetSymbolAddress((void**)&p_act_lo, g_act_lo);
    cudaGetSymbolAddress((void**)&p_w_hi, g_w_hi);
    cudaGetSymbolAddress((void**)&p_w_lo, g_w_lo);
    cudaGetSymbolAddress((void**)&p_WuT_hi, g_WuT_hi);
    cudaGetSymbolAddress((void**)&p_WuT_lo, g_WuT_lo);
    cudaGetSymbolAddress((void**)&p_WvT_hi, g_WvT_hi);
    cudaGetSymbolAddress((void**)&p_WvT_lo, g_WvT_lo);
    cudaGetSymbolAddress((void**)&p_WoT_hi, g_WoT_hi);
    cudaGetSymbolAddress((void**)&p_WoT_lo, g_WoT_lo);
    cudaGetSymbolAddress((void**)&p_W1T_hi, g_W1T_hi);
    cudaGetSymbolAddress((void**)&p_W1T_lo, g_W1T_lo);
    cudaGetSymbolAddress((void**)&p_W2T_hi, g_W2T_hi);
    cudaGetSymbolAddress((void**)&p_W2T_lo, g_W2T_lo);
    cudaGetSymbolAddress((void**)&p_W3T_hi, g_W3T_hi);
    cudaGetSymbolAddress((void**)&p_W3T_lo, g_W3T_lo);
    cudaGetSymbolAddress((void**)&p_WzT_hi, g_WzT_hi);
    cudaGetSymbolAddress((void**)&p_WzT_lo, g_WzT_lo);
    cudaGetSymbolAddress((void**)&p_u,    g_u);
    cudaGetSymbolAddress((void**)&p_vT,   g_vT);
    cudaGetSymbolAddress((void**)&p_conv, g_conv);
    cudaGetSymbolAddress((void**)&p_hcf,  g_hcf);
    cudaGetSymbolAddress((void**)&p_kT,   g_kT);
    cudaGetSymbolAddress((void**)&p_Ka,   g_Ka);

    const int FFT_SMEM = (2 * FFTN + FFTH) * sizeof(float2);   // 81920 B
    cudaFuncSetAttribute(ffta_kernel, cudaFuncAttributeMaxDynamicSharedMemorySize, FFT_SMEM);
    cudaFuncSetAttribute(conv_kernel, cudaFuncAttributeMaxDynamicSharedMemorySize, FFT_SMEM);
    cudaFuncSetAttribute(hgemm_kernel, cudaFuncAttributeMaxDynamicSharedMemorySize, GEMM_SMEM);

    dim3 t328(32, 8);

    // weight conversions (transpose + hi/lo split)
    convT_kernel<<<dim3(D1/32, DD/32), t328>>>(Wu, p_WuT_hi, p_WuT_lo, DD, D1);
    convT_kernel<<<dim3(D1/32, DD/32), t328>>>(Wv, p_WvT_hi, p_WvT_lo, DD, D1);
    convT_kernel<<<dim3(DD/32, D1/32), t328>>>(Wo, p_WoT_hi, p_WoT_lo, D1, DD);
    convT_kernel<<<dim3(EE/32, EE/32), t328>>>(W1, p_W1T_hi, p_W1T_lo, EE, EE);
    convT_kernel<<<dim3(EE/32, EE/32), t328>>>(W2, p_W2T_hi, p_W2T_lo, EE, EE);
    convT_kernel<<<dim3(EE/32, EE/32), t328>>>(W3, p_W3T_hi, p_W3T_lo, EE, EE);
    convT_kernel<<<dim3(NC/32, EE/32), t328>>>(Wz, p_WzT_hi, p_WzT_lo, EE, NC);

    // 1. xn = srms(x) -> hi/lo
    rmsnorm_bf16_kernel<<<ROWS, 128>>>(x, p_xn_hi, p_xn_lo, 0);

    // 2. u = silu(xn@Wu+bu); vT = silu(xn@Wv+bv) transposed per batch
    hgemm_kernel<<<dim3(D1/128, ROWS/128), 256, GEMM_SMEM>>>(
        p_xn_hi, p_xn_lo, p_WuT_hi, p_WuT_lo, bu, nullptr, p_u, ROWS, D1, DD, 1);
    hgemm_kernel<<<dim3(D1/128, ROWS/128), 256, GEMM_SMEM>>>(
        p_xn_hi, p_xn_lo, p_WvT_hi, p_WvT_lo, bv, nullptr, p_vT, ROWS, D1, DD, 2);

    // 3. position MLP -> kT (decayed, transposed)
    hcf_init_kernel<<<(NN*EE)/256, 256>>>(Wp, bp, p_hcf);
    const __nv_bfloat16* WTh[3] = {p_W1T_hi, p_W2T_hi, p_W3T_hi};
    const __nv_bfloat16* WTl[3] = {p_W1T_lo, p_W2T_lo, p_W3T_lo};
    const float* bs[3] = {b1, b2, b3};
    for (int l = 0; l < 3; l++) {
        rmsnorm_bf16_kernel<<<NN, 128>>>(p_hcf, p_act_hi, p_act_lo, 1);
        hgemm_kernel<<<dim3(EE/128, NN/128), 256, GEMM_SMEM>>>(
            p_act_hi, p_act_lo, WTh[l], WTl[l], bs[l], nullptr, p_hcf, NN, EE, EE, 0);
    }
    rmsnorm_bf16_kernel<<<NN, 128>>>(p_hcf, p_act_hi, p_act_lo, 1);
    hgemm_kernel<<<dim3(NC/128, NN/128), 256, GEMM_SMEM>>>(
        p_act_hi, p_act_lo, p_WzT_hi, p_WzT_lo, bz, nullptr, p_kT, NN, NC, EE, 4);

    // 4. Ka[c][f] = rfft(kT[c], 4096) / 4096
    ffta_kernel<<<NC/2, 512, FFT_SMEM>>>(p_kT, p_Ka);

    // 5. causal conv per channel-pair (FFT -> x Ka -> IFFT)
    conv_kernel<<<BB * NC / 2, 512, FFT_SMEM>>>(p_vT, p_Ka, p_conv);

    // 6. w = u * conv (transposed back), split to hi/lo
    mul_transpose_kernel<<<dim3(NN/32, NC/32, BB), t328>>>(p_conv, p_u, p_w_hi, p_w_lo);

    // 7. y = w @ Wo + bo + x
    hgemm_kernel<<<dim3(DD/128, ROWS/128), 256, GEMM_SMEM>>>(
        p_w_hi, p_w_lo, p_WoT_hi, p_WoT_lo, bo, x, y, ROWS, DD, D1, 3);
}

// round 7
// speedup vs baseline: 2.4696x; 1.1186x over previous
#include <cuda_runtime.h>
#include <cuda_bf16.h>
#include <math.h>
#include <stdint.h>

// ---------------------------------------------------------------------------
// Problem constants
// ---------------------------------------------------------------------------
#define BB 4
#define NN 2048
#define DD 512
#define D1 1024          // 2*D
#define EE 512
#define NC 1024          // H*HD channels
#define ROWS (BB*NN)     // 8192
#define FFTN 4096
#define FFTH 2048
#define KSTRIDE 2049
#define LOGG (-1.0005003335835335e-3f)   // ln(0.999)

// ---------------------------------------------------------------------------
// Scratch (__device__ globals; no allocation allowed)
// ---------------------------------------------------------------------------
__device__ __nv_bfloat16 g_xn_hi[ROWS * DD], g_xn_lo[ROWS * DD];
__device__ __nv_bfloat16 g_act_hi[NN * EE],  g_act_lo[NN * EE];
__device__ __nv_bfloat16 g_w_hi [ROWS * D1], g_w_lo [ROWS * D1];

__device__ __nv_bfloat16 g_WuT_hi[D1 * DD], g_WuT_lo[D1 * DD];
__device__ __nv_bfloat16 g_WvT_hi[D1 * DD], g_WvT_lo[D1 * DD];
__device__ __nv_bfloat16 g_WoT_hi[DD * D1], g_WoT_lo[DD * D1];
__device__ __nv_bfloat16 g_W1T_hi[EE * EE], g_W1T_lo[EE * EE];
__device__ __nv_bfloat16 g_W2T_hi[EE * EE], g_W2T_lo[EE * EE];
__device__ __nv_bfloat16 g_W3T_hi[EE * EE], g_W3T_lo[EE * EE];
__device__ __nv_bfloat16 g_WzT_hi[NC * EE], g_WzT_lo[NC * EE];

__device__ float  g_u   [ROWS * D1];
__device__ float  g_vT  [BB * NC * NN];
__device__ float  g_conv[BB * NC * NN];
__device__ float  g_hcf [NN * EE];
__device__ float  g_kT  [NC * NN];
__device__ float2 g_Ka  [NC * KSTRIDE];

// ---------------------------------------------------------------------------
// Helpers
// ---------------------------------------------------------------------------
__device__ __forceinline__ uint32_t smem_u32(const void* p) {
    uint32_t a;
    asm("{ .reg .u64 t; cvta.to.shared.u64 t, %1; cvt.u32.u64 %0, t; }"
        : "=r"(a) : "l"(p));
    return a;
}

__device__ __forceinline__ uint32_t packbf(float a, float b) {
    __nv_bfloat162 t;
    t.x = __float2bfloat16(a);
    t.y = __float2bfloat16(b);
    return *reinterpret_cast<uint32_t*>(&t);
}

__device__ __forceinline__ float2 cmul(float2 a, float2 b) {
    return make_float2(a.x*b.x - a.y*b.y, a.x*b.y + a.y*b.x);
}

__device__ __forceinline__ void ldmx4(uint32_t* r, uint32_t addr) {
    asm volatile("ldmatrix.sync.aligned.m8n8.x4.shared.b16 {%0,%1,%2,%3}, [%4];"
                 : "=r"(r[0]), "=r"(r[1]), "=r"(r[2]), "=r"(r[3]) : "r"(addr));
}
__device__ __forceinline__ void ldmx2(uint32_t* r, uint32_t addr) {
    asm volatile("ldmatrix.sync.aligned.m8n8.x2.shared.b16 {%0,%1}, [%2];"
                 : "=r"(r[0]), "=r"(r[1]) : "r"(addr));
}
__device__ __forceinline__ void mma16816(float* d, const uint32_t* a, const uint32_t* b) {
    asm volatile(
        "mma.sync.aligned.m16n8k16.row.col.f32.bf16.bf16.f32 "
        "{%0,%1,%2,%3}, {%4,%5,%6,%7}, {%8,%9}, {%0,%1,%2,%3};"
        : "+f"(d[0]), "+f"(d[1]), "+f"(d[2]), "+f"(d[3])
        : "r"(a[0]), "r"(a[1]), "r"(a[2]), "r"(a[3]), "r"(b[0]), "r"(b[1]));
}

// ---------------------------------------------------------------------------
// Row-wise srms (width 512) -> hi/lo bf16 split, optional relu.
// ---------------------------------------------------------------------------
__global__ void __launch_bounds__(128) rmsnorm_bf16_kernel(
    const float* __restrict__ in,
    __nv_bfloat16* __restrict__ hi, __nv_bfloat16* __restrict__ lo, int relu)
{
    size_t row = blockIdx.x;
    const float4* ip = (const float4*)(in + row * DD);
    float4 v = ip[threadIdx.x];
    float ss = v.x*v.x + v.y*v.y + v.z*v.z + v.w*v.w;
    #pragma unroll
    for (int o = 16; o; o >>= 1) ss += __shfl_xor_sync(0xffffffffu, ss, o);
    __shared__ float wsum[4];
    if ((threadIdx.x & 31) == 0) wsum[threadIdx.x >> 5] = ss;
    __syncthreads();
    float tot = wsum[0] + wsum[1] + wsum[2] + wsum[3];
    float inv = 1.0f / (sqrtf(tot * (1.0f / (float)DD)) + 1e-8f);
    float o4[4] = {v.x*inv, v.y*inv, v.z*inv, v.w*inv};
    if (relu) {
        #pragma unroll
        for (int i = 0; i < 4; i++) o4[i] = fmaxf(o4[i], 0.f);
    }
    float l4[4];
    #pragma unroll
    for (int i = 0; i < 4; i++)
        l4[i] = o4[i] - __bfloat162float(__float2bfloat16(o4[i]));
    size_t base = row * DD + threadIdx.x * 4;
    *(uint2*)(hi + base) = make_uint2(packbf(o4[0], o4[1]), packbf(o4[2], o4[3]));
    *(uint2*)(lo + base) = make_uint2(packbf(l4[0], l4[1]), packbf(l4[2], l4[3]));
}

// ---------------------------------------------------------------------------
// Weight transpose+convert: W[K][N] fp32 -> T_hi/T_lo [N][K] bf16
// ---------------------------------------------------------------------------
__global__ void convT_kernel(const float* __restrict__ W,
                             __nv_bfloat16* __restrict__ Thi,
                             __nv_bfloat16* __restrict__ Tlo, int K, int N)
{
    __shared__ float tile[32][33];
    int n0 = blockIdx.x * 32, k0 = blockIdx.y * 32;
    #pragma unroll
    for (int j = threadIdx.y; j < 32; j += 8)
        tile[j][threadIdx.x] = W[(size_t)(k0 + j) * N + n0 + threadIdx.x];
    __syncthreads();
    #pragma unroll
    for (int j = threadIdx.y; j < 32; j += 8) {
        float v = tile[threadIdx.x][j];
        __nv_bfloat16 h = __float2bfloat16(v);
        float r = v - __bfloat162float(h);
        size_t idx = (size_t)(n0 + j) * K + k0 + threadIdx.x;
        Thi[idx] = h;
        Tlo[idx] = __float2bfloat16(r);
    }
}

// ---------------------------------------------------------------------------
// hcf init: hcf[t,e] = t * Wp[e] + bp[e]
// ---------------------------------------------------------------------------
__global__ void hcf_init_kernel(const float* __restrict__ Wp,
                                const float* __restrict__ bp,
                                float* __restrict__ hcf)
{
    int i = blockIdx.x * blockDim.x + threadIdx.x;
    int t = i >> 9, e = i & 511;
    hcf[i] = (float)t * Wp[e] + bp[e];
}

// ---------------------------------------------------------------------------
// HMMA bf16-split GEMM: C[M,N] = (Ahi+Alo)[M,K] @ (Bhi+Blo)[N,K]^T + bias
// epi: 0 plain rowmajor / 1 silu rowmajor / 2 silu -> vT[b][c][n]
//      3 +resid rowmajor / 4 decay -> kT[c][t]
// ---------------------------------------------------------------------------
#define KC 64
#define TILE_B 16384                      // 128 rows x 128 bytes
#define GEMM_SMEM (128*132*4)             // fp32 C staging (67584 B) >= 4*TILE_B

__global__ void __launch_bounds__(256, 2)
hgemm_kernel(const __nv_bfloat16* __restrict__ Ahi, const __nv_bfloat16* __restrict__ Alo,
             const __nv_bfloat16* __restrict__ Bhi, const __nv_bfloat16* __restrict__ Blo,
             const float* __restrict__ bias, const float* __restrict__ resid,
             float* __restrict__ out, int M, int N, int K, int epi)
{
    extern __shared__ char smraw[];
    float* smC = (float*)smraw;
    const uint32_t sbase = smem_u32(smraw);

    const int tid = threadIdx.x, wid = tid >> 5, lane = tid & 31;
    const int m0 = blockIdx.y * 128, n0 = blockIdx.x * 128;
    const int wm = (wid & 3) * 32, wn = (wid >> 2) * 64;

    float acc[2][8][4];
    #pragma unroll
    for (int i = 0; i < 2; i++)
        #pragma unroll
        for (int j = 0; j < 8; j++)
            #pragma unroll
            for (int q = 0; q < 4; q++) acc[i][j][q] = 0.f;

    const int lr = tid >> 3;     // 0..31 (row group)
    const int lc = tid & 7;      // 16B chunk in row

    const int nch = K / KC;
    for (int ch = 0; ch < nch; ch++) {
        const int k0 = ch * KC;
        #pragma unroll
        for (int t4 = 0; t4 < 4; t4++) {
            const __nv_bfloat16* src =
                ((t4 == 0) ? Ahi : (t4 == 1) ? Alo : (t4 == 2) ? Bhi : Blo)
                + (size_t)((t4 < 2) ? m0 : n0) * K + k0 + lc * 8;
            uint32_t sdst = sbase + t4 * TILE_B;
            #pragma unroll
            for (int rr = 0; rr < 4; rr++) {
                int r = lr + rr * 32;
                uint32_t off = (uint32_t)(r * 128 + lc * 16);
                off ^= (off >> 3) & 0x70u;
                asm volatile("cp.async.cg.shared.global [%0], [%1], 16;"
                             :: "r"(sdst + off), "l"(src + (size_t)r * K) : "memory");
            }
        }
        asm volatile("cp.async.commit_group;" ::: "memory");
        asm volatile("cp.async.wait_group 0;" ::: "memory");
        __syncthreads();

        // ---- pass 1: AH x BH and AL x BH ----
        #pragma unroll
        for (int ks = 0; ks < 4; ks++) {
            uint32_t ah[2][4], al[2][4], bh[8][2];
            #pragma unroll
            for (int mt = 0; mt < 2; mt++) {
                uint32_t off = (uint32_t)((wm + mt*16 + (lane & 15)) * 128
                                          + ks * 32 + ((lane >> 4) & 1) * 16);
                off ^= (off >> 3) & 0x70u;
                ldmx4(ah[mt], sbase + off);
                ldmx4(al[mt], sbase + TILE_B + off);
            }
            #pragma unroll
            for (int nt = 0; nt < 8; nt++) {
                uint32_t off = (uint32_t)((wn + nt*8 + (lane & 7)) * 128
                                          + ks * 32 + ((lane >> 3) & 1) * 16);
                off ^= (off >> 3) & 0x70u;
                ldmx2(bh[nt], sbase + 2 * TILE_B + off);
            }
            #pragma unroll
            for (int mt = 0; mt < 2; mt++)
                #pragma unroll
                for (int nt = 0; nt < 8; nt++) {
                    mma16816(acc[mt][nt], ah[mt], bh[nt]);
                    mma16816(acc[mt][nt], al[mt], bh[nt]);
                }
        }
        // ---- pass 2: AH x BL ----
        #pragma unroll
        for (int ks = 0; ks < 4; ks++) {
            uint32_t ah[2][4], bl[8][2];
            #pragma unroll
            for (int mt = 0; mt < 2; mt++) {
                uint32_t off = (uint32_t)((wm + mt*16 + (lane & 15)) * 128
                                          + ks * 32 + ((lane >> 4) & 1) * 16);
                off ^= (off >> 3) & 0x70u;
                ldmx4(ah[mt], sbase + off);
            }
            #pragma unroll
            for (int nt = 0; nt < 8; nt++) {
                uint32_t off = (uint32_t)((wn + nt*8 + (lane & 7)) * 128
                                          + ks * 32 + ((lane >> 3) & 1) * 16);
                off ^= (off >> 3) & 0x70u;
                ldmx2(bl[nt], sbase + 3 * TILE_B + off);
            }
            #pragma unroll
            for (int mt = 0; mt < 2; mt++)
                #pragma unroll
                for (int nt = 0; nt < 8; nt++)
                    mma16816(acc[mt][nt], ah[mt], bl[nt]);
        }
        __syncthreads();
    }

    // ---- stage C in smem [128][132] fp32 ----
    #pragma unroll
    for (int mt = 0; mt < 2; mt++)
        #pragma unroll
        for (int nt = 0; nt < 8; nt++) {
            int r0 = wm + mt*16 + (lane >> 2);
            int c0 = wn + nt*8 + (lane & 3)*2;
            smC[r0*132 + c0]        = acc[mt][nt][0];
            smC[r0*132 + c0 + 1]    = acc[mt][nt][1];
            smC[(r0+8)*132 + c0]    = acc[mt][nt][2];
            smC[(r0+8)*132 + c0 + 1]= acc[mt][nt][3];
        }
    __syncthreads();

    if (epi == 0 || epi == 1 || epi == 3) {
        #pragma unroll 1
        for (int g = 0; g < 8; g++) {
            int row = g*16 + (tid >> 4);
            int col = (tid & 15) * 8;
            float vv[8];
            *(float4*)&vv[0] = *(float4*)&smC[row*132 + col];
            *(float4*)&vv[4] = *(float4*)&smC[row*132 + col + 4];
            const float* rp = (epi == 3) ? resid + (size_t)(m0+row)*N + n0 + col : nullptr;
            #pragma unroll
            for (int j = 0; j < 8; j++) {
                float c = vv[j] + bias[n0 + col + j];
                if (epi == 1) c = c / (1.0f + __expf(-c));
                else if (epi == 3) c += rp[j];
                vv[j] = c;
            }
            float* op = out + (size_t)(m0+row)*N + n0 + col;
            *(float4*)&op[0] = *(float4*)&vv[0];
            *(float4*)&op[4] = *(float4*)&vv[4];
        }
    } else {
        // epi 2: silu -> vT[b][c][n];  epi 4: decay -> kT[c][t]
        const int bb = m0 >> 11;
        const int nb = m0 & (NN - 1);
        #pragma unroll 1
        for (int g = 0; g < 16; g++) {
            int c  = (tid >> 5) * 16 + g;
            int nq = lane * 4;
            float b = bias[n0 + c];
            const float* cp = &smC[nq*132 + c];
            float vv[4] = { cp[0], cp[132], cp[264], cp[396] };
            if (epi == 2) {
                #pragma unroll
                for (int j = 0; j < 4; j++) {
                    float t = vv[j] + b;
                    vv[j] = t / (1.0f + __expf(-t));
                }
                float* op = out + (size_t)bb*NC*NN + (size_t)(n0+c)*NN + nb + nq;
                *(float4*)op = *(float4*)vv;
            } else {
                #pragma unroll
                for (int j = 0; j < 4; j++) {
                    int t = m0 + nq + j;
                    float fac = (t == 0) ? 1.0f : __expf((float)t * LOGG);
                    vv[j] = (vv[j] + b) * fac;
                }
                float* op = out + (size_t)(n0+c)*NN + m0 + nq;
                *(float4*)op = *(float4*)vv;
            }
        }
    }
}

// ---------------------------------------------------------------------------
// conv [b][c][n] * u [b][n][c] -> w_hi/w_lo bf16 [b][n][c]
// ---------------------------------------------------------------------------
__global__ void mul_transpose_kernel(const float* __restrict__ in,
                                     const float* __restrict__ u,
                                     __nv_bfloat16* __restrict__ whi,
                                     __nv_bfloat16* __restrict__ wlo)
{
    __shared__ float tile[32][33];
    size_t boff = (size_t)blockIdx.z * NC * NN;
    const float* inb = in + boff;
    const float* ub  = u  + boff;
    int x  = blockIdx.x * 32 + threadIdx.x;   // n
    int y0 = blockIdx.y * 32;                 // c
    #pragma unroll
    for (int j = threadIdx.y; j < 32; j += 8)
        tile[j][threadIdx.x] = inb[(size_t)(y0 + j) * NN + x];
    __syncthreads();
    int x2 = y0 + threadIdx.x;                // c
    int y2 = blockIdx.x * 32;                 // n base
    #pragma unroll
    for (int j = threadIdx.y; j < 32; j += 8) {
        int n = y2 + j;
        size_t idx = boff + (size_t)n * NC + x2;
        float f = tile[threadIdx.x][j] * ub[(size_t)n * NC + x2];
        __nv_bfloat16 h = __float2bfloat16(f);
        whi[idx] = h;
        wlo[idx] = __float2bfloat16(f - __bfloat162float(h));
    }
}

// ---------------------------------------------------------------------------
// 4096-pt Stockham radix-4 FFT in shared memory (512 threads, 6 stages).
// Butterfly verified against the 4-point DFT; tw[k] = exp(-2*pi*i*k/4096).
// Buffers ping-pong A->B->...->A (6 swaps, even).
// ---------------------------------------------------------------------------
__device__ __forceinline__ void fft4096_r4(float2* A, float2* Bb, const float2* tw,
                                           int tid, bool inv)
{
    float2* s = A; float2* d = Bb;
    int m = 1;
    const float sgn = inv ? -1.0f : 1.0f;
    #pragma unroll
    for (int stage = 0; stage < 6; stage++) {
        __syncthreads();
        #pragma unroll
        for (int it = 0; it < 2; it++) {
            int p = tid + it * 512;                 // butterfly id, 0..1023
            int jm = p & ~(m - 1);                  // twiddle base
            float2 a = s[p],        b  = s[p + 1024];
            float2 c = s[p + 2048], dd = s[p + 3072];
            float2 w1 = tw[jm];
            float2 w2 = tw[2 * jm];
            if (inv) { w1.y = -w1.y; w2.y = -w2.y; }
            float2 w3 = cmul(w1, w2);
            float2 ac  = make_float2(a.x + c.x,  a.y + c.y);
            float2 amc = make_float2(a.x - c.x,  a.y - c.y);
            float2 bd  = make_float2(b.x + dd.x, b.y + dd.y);
            float2 bmd = make_float2(b.x - dd.x, b.y - dd.y);
            // fwd: t1 = amc - i*bmd, t3 = amc + i*bmd   (inv: swapped)
            float2 t1 = make_float2(amc.x + sgn * bmd.y, amc.y - sgn * bmd.x);
            float2 t3 = make_float2(amc.x - sgn * bmd.y, amc.y + sgn * bmd.x);
            float2 t2 = make_float2(ac.x - bd.x, ac.y - bd.y);
            int ob = p + 3 * jm;
            d[ob]         = make_float2(ac.x + bd.x, ac.y + bd.y);
            d[ob + m]     = cmul(w1, t1);
            d[ob + 2*m]   = cmul(w2, t2);
            d[ob + 3*m]   = cmul(w3, t3);
        }
        float2* t = s; s = d; d = t;
        m <<= 2;
    }
    __syncthreads();
}

__device__ __forceinline__ void fill_tw(float2* tw, int tid)
{
    const float w0 = -1.5339807878856412e-3f;  // -2*pi/4096
    for (int k = tid; k < FFTH; k += 512) {
        float sv, cv;
        sincosf(w0 * (float)k, &sv, &cv);
        tw[k] = make_float2(cv, sv);
    }
}

__global__ void __launch_bounds__(512) ffta_kernel(
    const float* __restrict__ kT, float2* __restrict__ Ka)
{
    extern __shared__ float2 sm[];
    float2* A  = sm;
    float2* Bb = sm + FFTN;
    float2* tw = sm + 2*FFTN;
    int tid = threadIdx.x;
    int c0 = blockIdx.x * 2, c1 = c0 + 1;
    const float* ka = kT + (size_t)c0 * NN;
    const float* kb = ka + NN;
    for (int n2 = tid; n2 < NN; n2 += 512) A[n2] = make_float2(ka[n2], kb[n2]);
    for (int n2 = NN + tid; n2 < FFTN; n2 += 512) A[n2] = make_float2(0.f, 0.f);
    fill_tw(tw, tid);
    fft4096_r4(A, Bb, tw, tid, false);
    const float S = 1.0f / (float)FFTN;
    for (int f = tid; f <= FFTH; f += 512) {
        int fm = (FFTN - f) & (FFTN - 1);
        float2 Zf = A[f], Zm = A[fm];
        float2 Va = make_float2(0.5f*(Zf.x + Zm.x), 0.5f*(Zf.y - Zm.y));
        float2 Vb = make_float2(0.5f*(Zf.y + Zm.y), 0.5f*(Zm.x - Zf.x));
        Ka[(size_t)c0 * KSTRIDE + f] = make_float2(Va.x * S, Va.y * S);
        Ka[(size_t)c1 * KSTRIDE + f] = make_float2(Vb.x * S, Vb.y * S);
    }
}

__global__ void __launch_bounds__(512) conv_kernel(
    const float* __restrict__ vT, const float2* __restrict__ Ka,
    float* __restrict__ convT)
{
    extern __shared__ float2 sm[];
    float2* A  = sm;
    float2* Bb = sm + FFTN;
    float2* tw = sm + 2*FFTN;
    int tid = threadIdx.x;
    int idx = blockIdx.x;
    int b = idx >> 9, cc = idx & 511;
    int c0 = cc * 2, c1 = c0 + 1;
    const float* va = vT + ((size_t)b * NC + c0) * NN;
    const float* vb = va + NN;
    for (int n2 = tid; n2 < NN; n2 += 512) A[n2] = make_float2(va[n2], vb[n2]);
    for (int n2 = NN + tid; n2 < FFTN; n2 += 512) A[n2] = make_float2(0.f, 0.f);
    fill_tw(tw, tid);
    fft4096_r4(A, Bb, tw, tid, false);

    const float2* K0 = Ka + (size_t)c0 * KSTRIDE;
    const float2* K1 = Ka + (size_t)c1 * KSTRIDE;
    for (int f = tid; f <= FFTH; f += 512) {
        int fm = (FFTN - f) & (FFTN - 1);
        float2 Zf = A[f], Zm = A[fm];
        float2 Va = make_float2(0.5f*(Zf.x + Zm.x), 0.5f*(Zf.y - Zm.y));
        float2 Vb = make_float2(0.5f*(Zf.y + Zm.y), 0.5f*(Zm.x - Zf.x));
        float2 Ya = cmul(Va, K0[f]);
        float2 Yb = cmul(Vb, K1[f]);
        A[f] = make_float2(Ya.x - Yb.y, Ya.y + Yb.x);
        if (f != 0 && f != FFTH)
            A[fm] = make_float2(Ya.x + Yb.y, Yb.x - Ya.y);
    }
    fft4096_r4(A, Bb, tw, tid, true);

    float* oa = convT + ((size_t)b * NC + c0) * NN;
    for (int n2 = tid; n2 < NN; n2 += 512) {
        oa[n2]      = A[n2].x;
        oa[NN + n2] = A[n2].y;
    }
}

// ---------------------------------------------------------------------------
// Launch
// ---------------------------------------------------------------------------
extern "C" void kernel_launch(void* const* d_in, const int* in_sizes, int n_in,
                              void* d_out, int out_size)
{
    const float* x  = (const float*)d_in[0];
    const float* Wu = (const float*)d_in[1];
    const float* bu = (const float*)d_in[2];
    const float* Wv = (const float*)d_in[3];
    const float* bv = (const float*)d_in[4];
    const float* Wo = (const float*)d_in[5];
    const float* bo = (const float*)d_in[6];
    const float* Wp = (const float*)d_in[7];
    const float* bp = (const float*)d_in[8];
    const float* W1 = (const float*)d_in[9];
    const float* b1 = (const float*)d_in[10];
    const float* W2 = (const float*)d_in[11];
    const float* b2 = (const float*)d_in[12];
    const float* W3 = (const float*)d_in[13];
    const float* b3 = (const float*)d_in[14];
    const float* Wz = (const float*)d_in[15];
    const float* bz = (const float*)d_in[16];
    float* y = (float*)d_out;

    __nv_bfloat16 *p_xn_hi, *p_xn_lo, *p_act_hi, *p_act_lo, *p_w_hi, *p_w_lo;
    __nv_bfloat16 *p_WuT_hi, *p_WuT_lo, *p_WvT_hi, *p_WvT_lo, *p_WoT_hi, *p_WoT_lo;
    __nv_bfloat16 *p_W1T_hi, *p_W1T_lo, *p_W2T_hi, *p_W2T_lo, *p_W3T_hi, *p_W3T_lo;
    __nv_bfloat16 *p_WzT_hi, *p_WzT_lo;
    float *p_u, *p_vT, *p_conv, *p_hcf, *p_kT;
    float2 *p_Ka;

    cudaGetSymbolAddress((void**)&p_xn_hi, g_xn_hi);
    cudaGetSymbolAddress((void**)&p_xn_lo, g_xn_lo);
    cudaGetSymbolAddress((void**)&p_act_hi, g_act_hi);
    cudaGetSymbolAddress((void**)&p_act_lo, g_act_lo);
    cudaGetSymbolAddress((void**)&p_w_hi, g_w_hi);
    cudaGetSymbolAddress((void**)&p_w_lo, g_w_lo);
    cudaGetSymbolAddress((void**)&p_WuT_hi, g_WuT_hi);
    cudaGetSymbolAddress((void**)&p_WuT_lo, g_WuT_lo);
    cudaGetSymbolAddress((void**)&p_WvT_hi, g_WvT_hi);
    cudaGetSymbolAddress((void**)&p_WvT_lo, g_WvT_lo);
    cudaGetSymbolAddress((void**)&p_WoT_hi, g_WoT_hi);
    cudaGetSymbolAddress((void**)&p_WoT_lo, g_WoT_lo);
    cudaGetSymbolAddress((void**)&p_W1T_hi, g_W1T_hi);
    cudaGetSymbolAddress((void**)&p_W1T_lo, g_W1T_lo);
    cudaGetSymbolAddress((void**)&p_W2T_hi, g_W2T_hi);
    cudaGetSymbolAddress((void**)&p_W2T_lo, g_W2T_lo);
    cudaGetSymbolAddress((void**)&p_W3T_hi, g_W3T_hi);
    cudaGetSymbolAddress((void**)&p_W3T_lo, g_W3T_lo);
    cudaGetSymbolAddress((void**)&p_WzT_hi, g_WzT_hi);
    cudaGetSymbolAddress((void**)&p_WzT_lo, g_WzT_lo);
    cudaGetSymbolAddress((void**)&p_u,    g_u);
    cudaGetSymbolAddress((void**)&p_vT,   g_vT);
    cudaGetSymbolAddress((void**)&p_conv, g_conv);
    cudaGetSymbolAddress((void**)&p_hcf,  g_hcf);
    cudaGetSymbolAddress((void**)&p_kT,   g_kT);
    cudaGetSymbolAddress((void**)&p_Ka,   g_Ka);

    const int FFT_SMEM = (2 * FFTN + FFTH) * sizeof(float2);   // 81920 B
    cudaFuncSetAttribute(ffta_kernel, cudaFuncAttributeMaxDynamicSharedMemorySize, FFT_SMEM);
    cudaFuncSetAttribute(conv_kernel, cudaFuncAttributeMaxDynamicSharedMemorySize, FFT_SMEM);
    cudaFuncSetAttribute(hgemm_kernel, cudaFuncAttributeMaxDynamicSharedMemorySize, GEMM_SMEM);

    dim3 t328(32, 8);

    // weight conversions (transpose + hi/lo split)
    convT_kernel<<<dim3(D1/32, DD/32), t328>>>(Wu, p_WuT_hi, p_WuT_lo, DD, D1);
    convT_kernel<<<dim3(D1/32, DD/32), t328>>>(Wv, p_WvT_hi, p_WvT_lo, DD, D1);
    convT_kernel<<<dim3(DD/32, D1/32), t328>>>(Wo, p_WoT_hi, p_WoT_lo, D1, DD);
    convT_kernel<<<dim3(EE/32, EE/32), t328>>>(W1, p_W1T_hi, p_W1T_lo, EE, EE);
    convT_kernel<<<dim3(EE/32, EE/32), t328>>>(W2, p_W2T_hi, p_W2T_lo, EE, EE);
    convT_kernel<<<dim3(EE/32, EE/32), t328>>>(W3, p_W3T_hi, p_W3T_lo, EE, EE);
    convT_kernel<<<dim3(NC/32, EE/32), t328>>>(Wz, p_WzT_hi, p_WzT_lo, EE, NC);

    // 1. xn = srms(x) -> hi/lo
    rmsnorm_bf16_kernel<<<ROWS, 128>>>(x, p_xn_hi, p_xn_lo, 0);

    // 2. u = silu(xn@Wu+bu); vT = silu(xn@Wv+bv) transposed per batch
    hgemm_kernel<<<dim3(D1/128, ROWS/128), 256, GEMM_SMEM>>>(
        p_xn_hi, p_xn_lo, p_WuT_hi, p_WuT_lo, bu, nullptr, p_u, ROWS, D1, DD, 1);
    hgemm_kernel<<<dim3(D1/128, ROWS/128), 256, GEMM_SMEM>>>(
        p_xn_hi, p_xn_lo, p_WvT_hi, p_WvT_lo, bv, nullptr, p_vT, ROWS, D1, DD, 2);

    // 3. position MLP -> kT (decayed, transposed)
    hcf_init_kernel<<<(NN*EE)/256, 256>>>(Wp, bp, p_hcf);
    const __nv_bfloat16* WTh[3] = {p_W1T_hi, p_W2T_hi, p_W3T_hi};
    const __nv_bfloat16* WTl[3] = {p_W1T_lo, p_W2T_lo, p_W3T_lo};
    const float* bs[3] = {b1, b2, b3};
    for (int l = 0; l < 3; l++) {
        rmsnorm_bf16_kernel<<<NN, 128>>>(p_hcf, p_act_hi, p_act_lo, 1);
        hgemm_kernel<<<dim3(EE/128, NN/128), 256, GEMM_SMEM>>>(
            p_act_hi, p_act_lo, WTh[l], WTl[l], bs[l], nullptr, p_hcf, NN, EE, EE, 0);
    }
    rmsnorm_bf16_kernel<<<NN, 128>>>(p_hcf, p_act_hi, p_act_lo, 1);
    hgemm_kernel<<<dim3(NC/128, NN/128), 256, GEMM_SMEM>>>(
        p_act_hi, p_act_lo, p_WzT_hi, p_WzT_lo, bz, nullptr, p_kT, NN, NC, EE, 4);

    // 4. Ka[c][f] = rfft(kT[c], 4096) / 4096
    ffta_kernel<<<NC/2, 512, FFT_SMEM>>>(p_kT, p_Ka);

    // 5. causal conv per channel-pair (FFT -> x Ka -> IFFT)
    conv_kernel<<<BB * NC / 2, 512, FFT_SMEM>>>(p_vT, p_Ka, p_conv);

    // 6. w = u * conv (transposed back), split to hi/lo
    mul_transpose_kernel<<<dim3(NN/32, NC/32, BB), t328>>>(p_conv, p_u, p_w_hi, p_w_lo);

    // 7. y = w @ Wo + bo + x
    hgemm_kernel<<<dim3(DD/128, ROWS/128), 256, GEMM_SMEM>>>(
        p_w_hi, p_w_lo, p_WoT_hi, p_WoT_lo, bo, x, y, ROWS, DD, D1, 3);
}

// round 14
// speedup vs baseline: 2.8840x; 1.1678x over previous
#include <cuda_runtime.h>
#include <cuda_bf16.h>
#include <math.h>
#include <stdint.h>

// ---------------------------------------------------------------------------
// Problem constants
// ---------------------------------------------------------------------------
#define BB 4
#define NN 2048
#define DD 512
#define D1 1024          // 2*D
#define EE 512
#define NC 1024          // H*HD channels
#define ROWS (BB*NN)     // 8192
#define FFTN 4096
#define FFTH 2048
#define KSTRIDE 2049
#define LOGG (-1.0005003335835335e-3f)   // ln(0.999)

// ---------------------------------------------------------------------------
// Scratch (__device__ globals; no allocation allowed)
// ---------------------------------------------------------------------------
__device__ __nv_bfloat16 g_xn_hi[ROWS * DD], g_xn_lo[ROWS * DD];
__device__ __nv_bfloat16 g_act_hi[NN * EE],  g_act_lo[NN * EE];
__device__ __nv_bfloat16 g_w_hi [ROWS * D1], g_w_lo [ROWS * D1];

__device__ __nv_bfloat16 g_WuT_hi[D1 * DD], g_WuT_lo[D1 * DD];
__device__ __nv_bfloat16 g_WvT_hi[D1 * DD], g_WvT_lo[D1 * DD];
__device__ __nv_bfloat16 g_WoT_hi[DD * D1], g_WoT_lo[DD * D1];
__device__ __nv_bfloat16 g_W1T_hi[EE * EE], g_W1T_lo[EE * EE];
__device__ __nv_bfloat16 g_W2T_hi[EE * EE], g_W2T_lo[EE * EE];
__device__ __nv_bfloat16 g_W3T_hi[EE * EE], g_W3T_lo[EE * EE];
__device__ __nv_bfloat16 g_WzT_hi[NC * EE], g_WzT_lo[NC * EE];

__device__ float  g_u   [ROWS * D1];
__device__ float  g_vT  [BB * NC * NN];
__device__ float  g_conv[BB * NC * NN];
__device__ float  g_hcf [NN * EE];
__device__ float  g_kT  [NC * NN];
__device__ float2 g_Ka  [NC * KSTRIDE];

// ---------------------------------------------------------------------------
// Helpers
// ---------------------------------------------------------------------------
__device__ __forceinline__ uint32_t smem_u32(const void* p) {
    uint32_t a;
    asm("{ .reg .u64 t; cvta.to.shared.u64 t, %1; cvt.u32.u64 %0, t; }"
        : "=r"(a) : "l"(p));
    return a;
}

__device__ __forceinline__ uint32_t packbf(float a, float b) {
    __nv_bfloat162 t;
    t.x = __float2bfloat16(a);
    t.y = __float2bfloat16(b);
    return *reinterpret_cast<uint32_t*>(&t);
}

__device__ __forceinline__ float2 cmul(float2 a, float2 b) {
    return make_float2(a.x*b.x - a.y*b.y, a.x*b.y + a.y*b.x);
}

__device__ __forceinline__ void ldmx4(uint32_t* r, uint32_t addr) {
    asm volatile("ldmatrix.sync.aligned.m8n8.x4.shared.b16 {%0,%1,%2,%3}, [%4];"
                 : "=r"(r[0]), "=r"(r[1]), "=r"(r[2]), "=r"(r[3]) : "r"(addr));
}
__device__ __forceinline__ void ldmx2(uint32_t* r, uint32_t addr) {
    asm volatile("ldmatrix.sync.aligned.m8n8.x2.shared.b16 {%0,%1}, [%2];"
                 : "=r"(r[0]), "=r"(r[1]) : "r"(addr));
}
__device__ __forceinline__ void mma16816(float* d, const uint32_t* a, const uint32_t* b) {
    asm volatile(
        "mma.sync.aligned.m16n8k16.row.col.f32.bf16.bf16.f32 "
        "{%0,%1,%2,%3}, {%4,%5,%6,%7}, {%8,%9}, {%0,%1,%2,%3};"
        : "+f"(d[0]), "+f"(d[1]), "+f"(d[2]), "+f"(d[3])
        : "r"(a[0]), "r"(a[1]), "r"(a[2]), "r"(a[3]), "r"(b[0]), "r"(b[1]));
}

// ---------------------------------------------------------------------------
// Row-wise srms (width 512) -> hi/lo bf16 split, optional relu.
// ---------------------------------------------------------------------------
__global__ void __launch_bounds__(128) rmsnorm_bf16_kernel(
    const float* __restrict__ in,
    __nv_bfloat16* __restrict__ hi, __nv_bfloat16* __restrict__ lo, int relu)
{
    size_t row = blockIdx.x;
    const float4* ip = (const float4*)(in + row * DD);
    float4 v = ip[threadIdx.x];
    float ss = v.x*v.x + v.y*v.y + v.z*v.z + v.w*v.w;
    #pragma unroll
    for (int o = 16; o; o >>= 1) ss += __shfl_xor_sync(0xffffffffu, ss, o);
    __shared__ float wsum[4];
    if ((threadIdx.x & 31) == 0) wsum[threadIdx.x >> 5] = ss;
    __syncthreads();
    float tot = wsum[0] + wsum[1] + wsum[2] + wsum[3];
    float inv = 1.0f / (sqrtf(tot * (1.0f / (float)DD)) + 1e-8f);
    float o4[4] = {v.x*inv, v.y*inv, v.z*inv, v.w*inv};
    if (relu) {
        #pragma unroll
        for (int i = 0; i < 4; i++) o4[i] = fmaxf(o4[i], 0.f);
    }
    float l4[4];
    #pragma unroll
    for (int i = 0; i < 4; i++)
        l4[i] = o4[i] - __bfloat162float(__float2bfloat16(o4[i]));
    size_t base = row * DD + threadIdx.x * 4;
    *(uint2*)(hi + base) = make_uint2(packbf(o4[0], o4[1]), packbf(o4[2], o4[3]));
    *(uint2*)(lo + base) = make_uint2(packbf(l4[0], l4[1]), packbf(l4[2], l4[3]));
}

// ---------------------------------------------------------------------------
// Batched weight transpose+convert: 7 jobs, W[K][N] fp32 -> hi/lo [N][K] bf16
// ---------------------------------------------------------------------------
struct CTJobs {
    const float* W[7];
    __nv_bfloat16* Hi[7];
    __nv_bfloat16* Lo[7];
    int K[7], N[7];
    int base[8];
};

__global__ void __launch_bounds__(256) convT_all_kernel(CTJobs j)
{
    __shared__ float tile[32][33];
    int bid = blockIdx.x;
    int ji = 0;
    #pragma unroll
    for (int q = 1; q < 7; q++) if (bid >= j.base[q]) ji = q;
    int local = bid - j.base[ji];
    const int K = j.K[ji], N = j.N[ji];
    const float* W = j.W[ji];
    __nv_bfloat16* Thi = j.Hi[ji];
    __nv_bfloat16* Tlo = j.Lo[ji];
    int tx = N >> 5;
    int n0 = (local % tx) * 32, k0 = (local / tx) * 32;
    int lx = threadIdx.x & 31, ly = threadIdx.x >> 5;
    #pragma unroll
    for (int jj = ly; jj < 32; jj += 8)
        tile[jj][lx] = W[(size_t)(k0 + jj) * N + n0 + lx];
    __syncthreads();
    #pragma unroll
    for (int jj = ly; jj < 32; jj += 8) {
        float v = tile[lx][jj];
        __nv_bfloat16 h = __float2bfloat16(v);
        float r = v - __bfloat162float(h);
        size_t idx = (size_t)(n0 + jj) * K + k0 + lx;
        Thi[idx] = h;
        Tlo[idx] = __float2bfloat16(r);
    }
}

// ---------------------------------------------------------------------------
// hcf init: hcf[t,e] = t * Wp[e] + bp[e]
// ---------------------------------------------------------------------------
__global__ void hcf_init_kernel(const float* __restrict__ Wp,
                                const float* __restrict__ bp,
                                float* __restrict__ hcf)
{
    int i = blockIdx.x * blockDim.x + threadIdx.x;
    int t = i >> 9, e = i & 511;
    hcf[i] = (float)t * Wp[e] + bp[e];
}

// ---------------------------------------------------------------------------
// HMMA bf16-split GEMM: C[M,N] = (Ahi+Alo)[M,K] @ (Bhi+Blo)[N,K]^T + bias
// epi: 0 plain rowmajor / 1 silu rowmajor / 2 silu -> vT[b][c][n]
//      3 +resid rowmajor / 4 decay -> kT[c][t]
// ---------------------------------------------------------------------------
#define KC 64
#define TILE_B 16384                      // 128 rows x 128 bytes
#define GEMM_SMEM (128*132*4)             // fp32 C staging (67584 B) >= 4*TILE_B

__global__ void __launch_bounds__(256, 2)
hgemm_kernel(const __nv_bfloat16* __restrict__ Ahi, const __nv_bfloat16* __restrict__ Alo,
             const __nv_bfloat16* __restrict__ Bhi, const __nv_bfloat16* __restrict__ Blo,
             const float* __restrict__ bias, const float* __restrict__ resid,
             float* __restrict__ out, int M, int N, int K, int epi)
{
    extern __shared__ char smraw[];
    float* smC = (float*)smraw;
    const uint32_t sbase = smem_u32(smraw);

    const int tid = threadIdx.x, wid = tid >> 5, lane = tid & 31;
    const int m0 = blockIdx.y * 128, n0 = blockIdx.x * 128;
    const int wm = (wid & 3) * 32, wn = (wid >> 2) * 64;

    float acc[2][8][4];
    #pragma unroll
    for (int i = 0; i < 2; i++)
        #pragma unroll
        for (int j = 0; j < 8; j++)
            #pragma unroll
            for (int q = 0; q < 4; q++) acc[i][j][q] = 0.f;

    const int lr = tid >> 3;     // 0..31 (row group)
    const int lc = tid & 7;      // 16B chunk in row

    const int nch = K / KC;
    for (int ch = 0; ch < nch; ch++) {
        const int k0 = ch * KC;
        #pragma unroll
        for (int t4 = 0; t4 < 4; t4++) {
            const __nv_bfloat16* src =
                ((t4 == 0) ? Ahi : (t4 == 1) ? Alo : (t4 == 2) ? Bhi : Blo)
                + (size_t)((t4 < 2) ? m0 : n0) * K + k0 + lc * 8;
            uint32_t sdst = sbase + t4 * TILE_B;
            #pragma unroll
            for (int rr = 0; rr < 4; rr++) {
                int r = lr + rr * 32;
                uint32_t off = (uint32_t)(r * 128 + lc * 16);
                off ^= (off >> 3) & 0x70u;
                asm volatile("cp.async.cg.shared.global [%0], [%1], 16;"
                             :: "r"(sdst + off), "l"(src + (size_t)r * K) : "memory");
            }
        }
        asm volatile("cp.async.commit_group;" ::: "memory");
        asm volatile("cp.async.wait_group 0;" ::: "memory");
        __syncthreads();

        // ---- pass 1: AH x BH and AL x BH ----
        #pragma unroll
        for (int ks = 0; ks < 4; ks++) {
            uint32_t ah[2][4], al[2][4], bh[8][2];
            #pragma unroll
            for (int mt = 0; mt < 2; mt++) {
                uint32_t off = (uint32_t)((wm + mt*16 + (lane & 15)) * 128
                                          + ks * 32 + ((lane >> 4) & 1) * 16);
                off ^= (off >> 3) & 0x70u;
                ldmx4(ah[mt], sbase + off);
                ldmx4(al[mt], sbase + TILE_B + off);
            }
            #pragma unroll
            for (int nt = 0; nt < 8; nt++) {
                uint32_t off = (uint32_t)((wn + nt*8 + (lane & 7)) * 128
                                          + ks * 32 + ((lane >> 3) & 1) * 16);
                off ^= (off >> 3) & 0x70u;
                ldmx2(bh[nt], sbase + 2 * TILE_B + off);
            }
            #pragma unroll
            for (int mt = 0; mt < 2; mt++)
                #pragma unroll
                for (int nt = 0; nt < 8; nt++) {
                    mma16816(acc[mt][nt], ah[mt], bh[nt]);
                    mma16816(acc[mt][nt], al[mt], bh[nt]);
                }
        }
        // ---- pass 2: AH x BL ----
        #pragma unroll
        for (int ks = 0; ks < 4; ks++) {
            uint32_t ah[2][4], bl[8][2];
            #pragma unroll
            for (int mt = 0; mt < 2; mt++) {
                uint32_t off = (uint32_t)((wm + mt*16 + (lane & 15)) * 128
                                          + ks * 32 + ((lane >> 4) & 1) * 16);
                off ^= (off >> 3) & 0x70u;
                ldmx4(ah[mt], sbase + off);
            }
            #pragma unroll
            for (int nt = 0; nt < 8; nt++) {
                uint32_t off = (uint32_t)((wn + nt*8 + (lane & 7)) * 128
                                          + ks * 32 + ((lane >> 3) & 1) * 16);
                off ^= (off >> 3) & 0x70u;
                ldmx2(bl[nt], sbase + 3 * TILE_B + off);
            }
            #pragma unroll
            for (int mt = 0; mt < 2; mt++)
                #pragma unroll
                for (int nt = 0; nt < 8; nt++)
                    mma16816(acc[mt][nt], ah[mt], bl[nt]);
        }
        __syncthreads();
    }

    // ---- stage C in smem [128][132] fp32 ----
    #pragma unroll
    for (int mt = 0; mt < 2; mt++)
        #pragma unroll
        for (int nt = 0; nt < 8; nt++) {
            int r0 = wm + mt*16 + (lane >> 2);
            int c0 = wn + nt*8 + (lane & 3)*2;
            smC[r0*132 + c0]        = acc[mt][nt][0];
            smC[r0*132 + c0 + 1]    = acc[mt][nt][1];
            smC[(r0+8)*132 + c0]    = acc[mt][nt][2];
            smC[(r0+8)*132 + c0 + 1]= acc[mt][nt][3];
        }
    __syncthreads();

    if (epi == 0 || epi == 1 || epi == 3) {
        #pragma unroll 1
        for (int g = 0; g < 8; g++) {
            int row = g*16 + (tid >> 4);
            int col = (tid & 15) * 8;
            float vv[8];
            *(float4*)&vv[0] = *(float4*)&smC[row*132 + col];
            *(float4*)&vv[4] = *(float4*)&smC[row*132 + col + 4];
            const float* rp = (epi == 3) ? resid + (size_t)(m0+row)*N + n0 + col : nullptr;
            #pragma unroll
            for (int j = 0; j < 8; j++) {
                float c = vv[j] + bias[n0 + col + j];
                if (epi == 1) c = c / (1.0f + __expf(-c));
                else if (epi == 3) c += rp[j];
                vv[j] = c;
            }
            float* op = out + (size_t)(m0+row)*N + n0 + col;
            *(float4*)&op[0] = *(float4*)&vv[0];
            *(float4*)&op[4] = *(float4*)&vv[4];
        }
    } else {
        // epi 2: silu -> vT[b][c][n];  epi 4: decay -> kT[c][t]
        const int bb = m0 >> 11;
        const int nb = m0 & (NN - 1);
        #pragma unroll 1
        for (int g = 0; g < 16; g++) {
            int c  = (tid >> 5) * 16 + g;
            int nq = lane * 4;
            float b = bias[n0 + c];
            const float* cp = &smC[nq*132 + c];
            float vv[4] = { cp[0], cp[132], cp[264], cp[396] };
            if (epi == 2) {
                #pragma unroll
                for (int j = 0; j < 4; j++) {
                    float t = vv[j] + b;
                    vv[j] = t / (1.0f + __expf(-t));
                }
                float* op = out + (size_t)bb*NC*NN + (size_t)(n0+c)*NN + nb + nq;
                *(float4*)op = *(float4*)vv;
            } else {
                #pragma unroll
                for (int j = 0; j < 4; j++) {
                    int t = m0 + nq + j;
                    float fac = (t == 0) ? 1.0f : __expf((float)t * LOGG);
                    vv[j] = (vv[j] + b) * fac;
                }
                float* op = out + (size_t)(n0+c)*NN + m0 + nq;
                *(float4*)op = *(float4*)vv;
            }
        }
    }
}

// ---------------------------------------------------------------------------
// conv [b][c][n] * u [b][n][c] -> w_hi/w_lo bf16 [b][n][c]
// ---------------------------------------------------------------------------
__global__ void mul_transpose_kernel(const float* __restrict__ in,
                                     const float* __restrict__ u,
                                     __nv_bfloat16* __restrict__ whi,
                                     __nv_bfloat16* __restrict__ wlo)
{
    __shared__ float tile[32][33];
    size_t boff = (size_t)blockIdx.z * NC * NN;
    const float* inb = in + boff;
    const float* ub  = u  + boff;
    int x  = blockIdx.x * 32 + threadIdx.x;   // n
    int y0 = blockIdx.y * 32;                 // c
    #pragma unroll
    for (int j = threadIdx.y; j < 32; j += 8)
        tile[j][threadIdx.x] = inb[(size_t)(y0 + j) * NN + x];
    __syncthreads();
    int x2 = y0 + threadIdx.x;                // c
    int y2 = blockIdx.x * 32;                 // n base
    #pragma unroll
    for (int j = threadIdx.y; j < 32; j += 8) {
        int n = y2 + j;
        size_t idx = boff + (size_t)n * NC + x2;
        float f = tile[threadIdx.x][j] * ub[(size_t)n * NC + x2];
        __nv_bfloat16 h = __float2bfloat16(f);
        whi[idx] = h;
        wlo[idx] = __float2bfloat16(f - __bfloat162float(h));
    }
}

// ---------------------------------------------------------------------------
// 4096-pt Stockham radix-4 FFT in shared memory (512 threads, 6 stages).
// ---------------------------------------------------------------------------
__device__ __forceinline__ void fft4096_r4(float2* A, float2* Bb, const float2* tw,
                                           int tid, bool inv)
{
    float2* s = A; float2* d = Bb;
    int m = 1;
    const float sgn = inv ? -1.0f : 1.0f;
    #pragma unroll
    for (int stage = 0; stage < 6; stage++) {
        __syncthreads();
        #pragma unroll
        for (int it = 0; it < 2; it++) {
            int p = tid + it * 512;                 // butterfly id, 0..1023
            int jm = p & ~(m - 1);                  // twiddle base
            float2 a = s[p],        b  = s[p + 1024];
            float2 c = s[p + 2048], dd = s[p + 3072];
            float2 w1 = tw[jm];
            float2 w2 = tw[2 * jm];
            if (inv) { w1.y = -w1.y; w2.y = -w2.y; }
            float2 w3 = cmul(w1, w2);
            float2 ac  = make_float2(a.x + c.x,  a.y + c.y);
            float2 amc = make_float2(a.x - c.x,  a.y - c.y);
            float2 bd  = make_float2(b.x + dd.x, b.y + dd.y);
            float2 bmd = make_float2(b.x - dd.x, b.y - dd.y);
            float2 t1 = make_float2(amc.x + sgn * bmd.y, amc.y - sgn * bmd.x);
            float2 t3 = make_float2(amc.x - sgn * bmd.y, amc.y + sgn * bmd.x);
            float2 t2 = make_float2(ac.x - bd.x, ac.y - bd.y);
            int ob = p + 3 * jm;
            d[ob]         = make_float2(ac.x + bd.x, ac.y + bd.y);
            d[ob + m]     = cmul(w1, t1);
            d[ob + 2*m]   = cmul(w2, t2);
            d[ob + 3*m]   = cmul(w3, t3);
        }
        float2* t = s; s = d; d = t;
        m <<= 2;
    }
    __syncthreads();
}

__device__ __forceinline__ void fill_tw(float2* tw, int tid)
{
    const float w0 = -1.5339807878856412e-3f;  // -2*pi/4096
    for (int k = tid; k < FFTH; k += 512) {
        float sv, cv;
        sincosf(w0 * (float)k, &sv, &cv);
        tw[k] = make_float2(cv, sv);
    }
}

__global__ void __launch_bounds__(512) ffta_kernel(
    const float* __restrict__ kT, float2* __restrict__ Ka)
{
    extern __shared__ float2 sm[];
    float2* A  = sm;
    float2* Bb = sm + FFTN;
    float2* tw = sm + 2*FFTN;
    int tid = threadIdx.x;
    int c0 = blockIdx.x * 2, c1 = c0 + 1;
    const float* ka = kT + (size_t)c0 * NN;
    const float* kb = ka + NN;
    for (int n2 = tid; n2 < NN; n2 += 512) A[n2] = make_float2(ka[n2], kb[n2]);
    for (int n2 = NN + tid; n2 < FFTN; n2 += 512) A[n2] = make_float2(0.f, 0.f);
    fill_tw(tw, tid);
    fft4096_r4(A, Bb, tw, tid, false);
    const float S = 1.0f / (float)FFTN;
    for (int f = tid; f <= FFTH; f += 512) {
        int fm = (FFTN - f) & (FFTN - 1);
        float2 Zf = A[f], Zm = A[fm];
        float2 Va = make_float2(0.5f*(Zf.x + Zm.x), 0.5f*(Zf.y - Zm.y));
        float2 Vb = make_float2(0.5f*(Zf.y + Zm.y), 0.5f*(Zm.x - Zf.x));
        Ka[(size_t)c0 * KSTRIDE + f] = make_float2(Va.x * S, Va.y * S);
        Ka[(size_t)c1 * KSTRIDE + f] = make_float2(Vb.x * S, Vb.y * S);
    }
}

__global__ void __launch_bounds__(512) conv_kernel(
    const float* __restrict__ vT, const float2* __restrict__ Ka,
    float* __restrict__ convT)
{
    extern __shared__ float2 sm[];
    float2* A  = sm;
    float2* Bb = sm + FFTN;
    float2* tw = sm + 2*FFTN;
    int tid = threadIdx.x;
    int idx = blockIdx.x;
    int b = idx >> 9, cc = idx & 511;
    int c0 = cc * 2, c1 = c0 + 1;
    const float* va = vT + ((size_t)b * NC + c0) * NN;
    const float* vb = va + NN;
    for (int n2 = tid; n2 < NN; n2 += 512) A[n2] = make_float2(va[n2], vb[n2]);
    for (int n2 = NN + tid; n2 < FFTN; n2 += 512) A[n2] = make_float2(0.f, 0.f);
    fill_tw(tw, tid);
    fft4096_r4(A, Bb, tw, tid, false);

    const float2* K0 = Ka + (size_t)c0 * KSTRIDE;
    const float2* K1 = Ka + (size_t)c1 * KSTRIDE;
    for (int f = tid; f <= FFTH; f += 512) {
        int fm = (FFTN - f) & (FFTN - 1);
        float2 Zf = A[f], Zm = A[fm];
        float2 Va = make_float2(0.5f*(Zf.x + Zm.x), 0.5f*(Zf.y - Zm.y));
        float2 Vb = make_float2(0.5f*(Zf.y + Zm.y), 0.5f*(Zm.x - Zf.x));
        float2 Ya = cmul(Va, K0[f]);
        float2 Yb = cmul(Vb, K1[f]);
        A[f] = make_float2(Ya.x - Yb.y, Ya.y + Yb.x);
        if (f != 0 && f != FFTH)
            A[fm] = make_float2(Ya.x + Yb.y, Yb.x - Ya.y);
    }
    fft4096_r4(A, Bb, tw, tid, true);

    float* oa = convT + ((size_t)b * NC + c0) * NN;
    for (int n2 = tid; n2 < NN; n2 += 512) {
        oa[n2]      = A[n2].x;
        oa[NN + n2] = A[n2].y;
    }
}

// ---------------------------------------------------------------------------
// Launch
// ---------------------------------------------------------------------------
extern "C" void kernel_launch(void* const* d_in, const int* in_sizes, int n_in,
                              void* d_out, int out_size)
{
    const float* x  = (const float*)d_in[0];
    const float* Wu = (const float*)d_in[1];
    const float* bu = (const float*)d_in[2];
    const float* Wv = (const float*)d_in[3];
    const float* bv = (const float*)d_in[4];
    const float* Wo = (const float*)d_in[5];
    const float* bo = (const float*)d_in[6];
    const float* Wp = (const float*)d_in[7];
    const float* bp = (const float*)d_in[8];
    const float* W1 = (const float*)d_in[9];
    const float* b1 = (const float*)d_in[10];
    const float* W2 = (const float*)d_in[11];
    const float* b2 = (const float*)d_in[12];
    const float* W3 = (const float*)d_in[13];
    const float* b3 = (const float*)d_in[14];
    const float* Wz = (const float*)d_in[15];
    const float* bz = (const float*)d_in[16];
    float* y = (float*)d_out;

    __nv_bfloat16 *p_xn_hi, *p_xn_lo, *p_act_hi, *p_act_lo, *p_w_hi, *p_w_lo;
    __nv_bfloat16 *p_WuT_hi, *p_WuT_lo, *p_WvT_hi, *p_WvT_lo, *p_WoT_hi, *p_WoT_lo;
    __nv_bfloat16 *p_W1T_hi, *p_W1T_lo, *p_W2T_hi, *p_W2T_lo, *p_W3T_hi, *p_W3T_lo;
    __nv_bfloat16 *p_WzT_hi, *p_WzT_lo;
    float *p_u, *p_vT, *p_conv, *p_hcf, *p_kT;
    float2 *p_Ka;

    cudaGetSymbolAddress((void**)&p_xn_hi, g_xn_hi);
    cudaGetSymbolAddress((void**)&p_xn_lo, g_xn_lo);
    cudaGetSymbolAddress((void**)&p_act_hi, g_act_hi);
    cudaGetSymbolAddress((void**)&p_act_lo, g_act_lo);
    cudaGetSymbolAddress((void**)&p_w_hi, g_w_hi);
    cudaGetSymbolAddress((void**)&p_w_lo, g_w_lo);
    cudaGetSymbolAddress((void**)&p_WuT_hi, g_WuT_hi);
    cudaGetSymbolAddress((void**)&p_WuT_lo, g_WuT_lo);
    cudaGetSymbolAddress((void**)&p_WvT_hi, g_WvT_hi);
    cudaGetSymbolAddress((void**)&p_WvT_lo, g_WvT_lo);
    cudaGetSymbolAddress((void**)&p_WoT_hi, g_WoT_hi);
    cudaGetSymbolAddress((void**)&p_WoT_lo, g_WoT_lo);
    cudaGetSymbolAddress((void**)&p_W1T_hi, g_W1T_hi);
    cudaGetSymbolAddress((void**)&p_W1T_lo, g_W1T_lo);
    cudaGetSymbolAddress((void**)&p_W2T_hi, g_W2T_hi);
    cudaGetSymbolAddress((void**)&p_W2T_lo, g_W2T_lo);
    cudaGetSymbolAddress((void**)&p_W3T_hi, g_W3T_hi);
    cudaGetSymbolAddress((void**)&p_W3T_lo, g_W3T_lo);
    cudaGetSymbolAddress((void**)&p_WzT_hi, g_WzT_hi);
    cudaGetSymbolAddress((void**)&p_WzT_lo, g_WzT_lo);
    cudaGetSymbolAddress((void**)&p_u,    g_u);
    cudaGetSymbolAddress((void**)&p_vT,   g_vT);
    cudaGetSymbolAddress((void**)&p_conv, g_conv);
    cudaGetSymbolAddress((void**)&p_hcf,  g_hcf);
    cudaGetSymbolAddress((void**)&p_kT,   g_kT);
    cudaGetSymbolAddress((void**)&p_Ka,   g_Ka);

    const int FFT_SMEM = (2 * FFTN + FFTH) * sizeof(float2);   // 81920 B
    cudaFuncSetAttribute(ffta_kernel, cudaFuncAttributeMaxDynamicSharedMemorySize, FFT_SMEM);
    cudaFuncSetAttribute(conv_kernel, cudaFuncAttributeMaxDynamicSharedMemorySize, FFT_SMEM);
    cudaFuncSetAttribute(hgemm_kernel, cudaFuncAttributeMaxDynamicSharedMemorySize, GEMM_SMEM);

    // side stream + fork/join events (created per call; few calls total, no
    // device memory involved; never destroyed while capture may be active)
    cudaStream_t s1;
    cudaStreamCreateWithFlags(&s1, cudaStreamNonBlocking);
    cudaEvent_t eF, eJ;
    cudaEventCreateWithFlags(&eF, cudaEventDisableTiming);
    cudaEventCreateWithFlags(&eJ, cudaEventDisableTiming);

    // ---- prologue on main stream: batched weight conversion + big rmsnorm ----
    CTJobs jobs;
    const float* Ws_[7]        = {Wu, Wv, Wo, W1, W2, W3, Wz};
    __nv_bfloat16* Hi_[7]      = {p_WuT_hi, p_WvT_hi, p_WoT_hi, p_W1T_hi, p_W2T_hi, p_W3T_hi, p_WzT_hi};
    __nv_bfloat16* Lo_[7]      = {p_WuT_lo, p_WvT_lo, p_WoT_lo, p_W1T_lo, p_W2T_lo, p_W3T_lo, p_WzT_lo};
    int Ks_[7] = {DD, DD, D1, EE, EE, EE, EE};
    int Ns_[7] = {D1, D1, DD, EE, EE, EE, NC};
    int acc = 0;
    for (int q = 0; q < 7; q++) {
        jobs.W[q] = Ws_[q]; jobs.Hi[q] = Hi_[q]; jobs.Lo[q] = Lo_[q];
        jobs.K[q] = Ks_[q]; jobs.N[q] = Ns_[q];
        jobs.base[q] = acc;
        acc += (Ns_[q] / 32) * (Ks_[q] / 32);
    }
    jobs.base[7] = acc;
    convT_all_kernel<<<acc, 256>>>(jobs);
    rmsnorm_bf16_kernel<<<ROWS, 128>>>(x, p_xn_hi, p_xn_lo, 0);

    // ---- fork: s1 runs the position-MLP chain + ffta ----
    cudaEventRecord(eF, 0);
    cudaStreamWaitEvent(s1, eF, 0);

    // main stream: u/v GEMMs
    hgemm_kernel<<<dim3(D1/128, ROWS/128), 256, GEMM_SMEM>>>(
        p_xn_hi, p_xn_lo, p_WuT_hi, p_WuT_lo, bu, nullptr, p_u, ROWS, D1, DD, 1);
    hgemm_kernel<<<dim3(D1/128, ROWS/128), 256, GEMM_SMEM>>>(
        p_xn_hi, p_xn_lo, p_WvT_hi, p_WvT_lo, bv, nullptr, p_vT, ROWS, D1, DD, 2);

    // s1: position MLP -> kT -> Ka
    hcf_init_kernel<<<(NN*EE)/256, 256, 0, s1>>>(Wp, bp, p_hcf);
    const __nv_bfloat16* WTh[3] = {p_W1T_hi, p_W2T_hi, p_W3T_hi};
    const __nv_bfloat16* WTl[3] = {p_W1T_lo, p_W2T_lo, p_W3T_lo};
    const float* bs[3] = {b1, b2, b3};
    for (int l = 0; l < 3; l++) {
        rmsnorm_bf16_kernel<<<NN, 128, 0, s1>>>(p_hcf, p_act_hi, p_act_lo, 1);
        hgemm_kernel<<<dim3(EE/128, NN/128), 256, GEMM_SMEM, s1>>>(
            p_act_hi, p_act_lo, WTh[l], WTl[l], bs[l], nullptr, p_hcf, NN, EE, EE, 0);
    }
    rmsnorm_bf16_kernel<<<NN, 128, 0, s1>>>(p_hcf, p_act_hi, p_act_lo, 1);
    hgemm_kernel<<<dim3(NC/128, NN/128), 256, GEMM_SMEM, s1>>>(
        p_act_hi, p_act_lo, p_WzT_hi, p_WzT_lo, bz, nullptr, p_kT, NN, NC, EE, 4);
    ffta_kernel<<<NC/2, 512, FFT_SMEM, s1>>>(p_kT, p_Ka);

    // ---- join: conv needs vT (main) + Ka (s1) ----
    cudaEventRecord(eJ, s1);
    cudaStreamWaitEvent(0, eJ, 0);

    conv_kernel<<<BB * NC / 2, 512, FFT_SMEM>>>(p_vT, p_Ka, p_conv);

    mul_transpose_kernel<<<dim3(NN/32, NC/32, BB), dim3(32, 8)>>>(p_conv, p_u, p_w_hi, p_w_lo);

    hgemm_kernel<<<dim3(DD/128, ROWS/128), 256, GEMM_SMEM>>>(
        p_w_hi, p_w_lo, p_WoT_hi, p_WoT_lo, bo, x, y, ROWS, DD, D1, 3);
}